// round 2
// baseline (speedup 1.0000x reference)
#include <cuda_runtime.h>
#include <math.h>

#define BB 64
#define NN 4096
#define FEAT 256
#define NS 6
#define SD 64
#define NCHUNK 8

// ---------------- scratch (device globals: no allocs allowed) ----------------
__device__ float g_k[BB * NN * SD];          // 64 MB
__device__ float g_v[BB * NN * SD];          // 64 MB
__device__ float g_Wt[FEAT * 128];           // [d][c] c<64 -> Wk col, c>=64 -> Wv
__device__ float g_WqT[SD * SD];             // [h][g]
__device__ float g_WihT[SD * 192];           // [h][c]
__device__ float g_WhhT[SD * 192];           // [h][c]
__device__ float g_W1T[SD * 128];            // [h][c]
__device__ float g_W2T[128 * SD];            // [c][h]
__device__ float g_slots[BB * NS * SD];
__device__ float g_q[BB * NS * SD];
__device__ float g_pU[BB * NCHUNK * NS * SD];
__device__ float g_pS[BB * NCHUNK * NS];

__device__ __forceinline__ void warp_red2(float& a, float& b) {
#pragma unroll
    for (int o = 16; o; o >>= 1) {
        a += __shfl_xor_sync(0xffffffffu, a, o);
        b += __shfl_xor_sync(0xffffffffu, b, o);
    }
}

// ---------------- kernel 0: transpose small weights ----------------
__global__ void transpose_kernel(const float* __restrict__ Wk, const float* __restrict__ Wv,
                                 const float* __restrict__ Wq, const float* __restrict__ Wih,
                                 const float* __restrict__ Whh, const float* __restrict__ W1,
                                 const float* __restrict__ W2) {
    int tid = blockIdx.x * 256 + threadIdx.x;
    const int stride = 64 * 256;
    for (int idx = tid; idx < FEAT * 128; idx += stride) {
        int d = idx >> 7, c = idx & 127;
        g_Wt[idx] = (c < 64) ? Wk[c * FEAT + d] : Wv[(c - 64) * FEAT + d];
    }
    for (int idx = tid; idx < SD * SD; idx += stride) {
        int h = idx >> 6, g = idx & 63;
        g_WqT[idx] = Wq[g * SD + h];
    }
    for (int idx = tid; idx < SD * 192; idx += stride) {
        int h = idx / 192, c = idx % 192;
        g_WihT[idx] = Wih[c * SD + h];
        g_WhhT[idx] = Whh[c * SD + h];
    }
    for (int idx = tid; idx < SD * 128; idx += stride) {
        int h = idx >> 7, c = idx & 127;
        g_W1T[idx] = W1[c * SD + h];
    }
    for (int idx = tid; idx < 128 * SD; idx += stride) {
        int c = idx >> 6, h = idx & 63;
        g_W2T[idx] = W2[h * 128 + c];
    }
}

// ---------------- kernel 1: slots init + q0 ----------------
__global__ __launch_bounds__(384) void init_kernel(const float* __restrict__ noise,
                                                   const float* __restrict__ mu,
                                                   const float* __restrict__ sigma,
                                                   const float* __restrict__ lng,
                                                   const float* __restrict__ lnb) {
    __shared__ float sln[NS * SD];
    __shared__ float red[12][2];
    int b = blockIdx.x;
    int t = threadIdx.x;
    int s = t >> 6, h = t & 63;
    int wid = t >> 5, lane = t & 31;

    float sv = mu[h] + sigma[h] * noise[b * 384 + t];
    g_slots[b * 384 + t] = sv;

    float sum = sv, sq = sv * sv;
    warp_red2(sum, sq);
    if (lane == 0) { red[wid][0] = sum; red[wid][1] = sq; }
    __syncthreads();
    float tsum = red[2 * s][0] + red[2 * s + 1][0];
    float tsq = red[2 * s][1] + red[2 * s + 1][1];
    float m = tsum * (1.f / 64.f);
    float var = tsq * (1.f / 64.f) - m * m;
    float rstd = rsqrtf(var + 1e-5f);
    sln[t] = (sv - m) * rstd * lng[h] + lnb[h];
    __syncthreads();
    float qv = 0.f;
#pragma unroll
    for (int hh = 0; hh < SD; hh++) qv += sln[s * SD + hh] * g_WqT[hh * SD + h];
    g_q[b * 384 + t] = qv;
}

// ---------------- kernel 2: fused feature-LN + K/V projection (f32x2 GEMM) ----------------
#define PJ_STRIDE 130
__global__ __launch_bounds__(256) void proj_kernel(const float* __restrict__ feat,
                                                   const float* __restrict__ lg,
                                                   const float* __restrict__ lb) {
    extern __shared__ float smem[];
    float* At = smem;                    // [256][130] transposed, LN'd A-tile
    float* Ws = At + FEAT * PJ_STRIDE;   // [32][128]
    float* stat = Ws + 32 * 128;         // [128][2] mean,rstd
    float* sg = stat + 256;              // [256]
    float* sb = sg + 256;                // [256]

    int t = threadIdx.x;                 // t == feature dim d for load phases
    unsigned base = blockIdx.x * (128u * FEAT);

    sg[t] = lg[t];
    sb[t] = lb[t];

    // load transposed: At[d][row]
#pragma unroll 8
    for (int row = 0; row < 128; row++)
        At[t * PJ_STRIDE + row] = feat[base + row * FEAT + t];
    __syncthreads();

    // per-row LN stats (warp per row)
    {
        int w = t >> 5, lane = t & 31;
        for (int i = 0; i < 16; i++) {
            int row = w * 16 + i;
            float sum = 0.f, sq = 0.f;
#pragma unroll
            for (int j = 0; j < 8; j++) {
                float x = At[(lane + 32 * j) * PJ_STRIDE + row];
                sum += x; sq += x * x;
            }
            warp_red2(sum, sq);
            if (lane == 0) {
                float m = sum * (1.f / 256.f);
                float var = sq * (1.f / 256.f) - m * m;
                stat[2 * row] = m;
                stat[2 * row + 1] = rsqrtf(var + 1e-5f);
            }
        }
    }
    __syncthreads();

    // normalize in smem
#pragma unroll 8
    for (int row = 0; row < 128; row++) {
        float x = At[t * PJ_STRIDE + row];
        At[t * PJ_STRIDE + row] = (x - stat[2 * row]) * stat[2 * row + 1] * sg[t] + sb[t];
    }
    __syncthreads();

    // GEMM: 128 rows x 128 cols, K=256; thread = (tx,ty) 16x16; 8 rows x 8 cols each (row pairs as f32x2)
    int tx = t & 15, ty = t >> 4;
    unsigned long long acc[4][8];
#pragma unroll
    for (int i = 0; i < 4; i++)
#pragma unroll
        for (int j = 0; j < 8; j++) acc[i][j] = 0ULL;

    for (int k0 = 0; k0 < FEAT; k0 += 32) {
#pragma unroll
        for (int it = 0; it < 4; it++) {
            int i4 = it * 256 + t;
            ((float4*)Ws)[i4] = ((const float4*)(g_Wt + k0 * 128))[i4];
        }
        __syncthreads();
#pragma unroll
        for (int k = 0; k < 32; k++) {
            const float* ar = At + (k0 + k) * PJ_STRIDE;
            unsigned long long a2[4];
#pragma unroll
            for (int i = 0; i < 4; i++)
                a2[i] = *(const unsigned long long*)(ar + 2 * (tx + 16 * i));
            float wv[8];
            *(float4*)(wv) = *(const float4*)(Ws + k * 128 + ty * 8);
            *(float4*)(wv + 4) = *(const float4*)(Ws + k * 128 + ty * 8 + 4);
            unsigned long long wd[8];
#pragma unroll
            for (int j = 0; j < 8; j++)
                asm("mov.b64 %0, {%1, %1};" : "=l"(wd[j]) : "f"(wv[j]));
#pragma unroll
            for (int i = 0; i < 4; i++)
#pragma unroll
                for (int j = 0; j < 8; j++)
                    asm("fma.rn.f32x2 %0, %1, %2, %0;" : "+l"(acc[i][j]) : "l"(a2[i]), "l"(wd[j]));
        }
        __syncthreads();
    }

    // epilogue
    unsigned mbase = blockIdx.x * 128u;
    float* dst = (ty < 8) ? g_k : g_v;
    int cc = (ty & 7) * 8;
#pragma unroll
    for (int i = 0; i < 4; i++) {
        int r0 = 2 * tx + 32 * i;
#pragma unroll
        for (int rr = 0; rr < 2; rr++) {
            float vals[8];
#pragma unroll
            for (int j = 0; j < 8; j++) {
                unsigned long long u = acc[i][j];
                unsigned w = rr ? (unsigned)(u >> 32) : (unsigned)(u & 0xffffffffULL);
                vals[j] = __uint_as_float(w);
            }
            unsigned mrow = mbase + r0 + rr;
            *(float4*)(dst + (size_t)mrow * SD + cc) = make_float4(vals[0], vals[1], vals[2], vals[3]);
            *(float4*)(dst + (size_t)mrow * SD + cc + 4) = make_float4(vals[4], vals[5], vals[6], vals[7]);
        }
    }
}

// ---------------- kernel 3: fused attention pass (one n-chunk per block) ----------------
__global__ __launch_bounds__(384) void attn_kernel() {
    __shared__ float qs[NS * SD];
    __shared__ float kT[SD * 65];     // [d][n] padded
    __shared__ float vs[64 * SD];     // [n][h]
    __shared__ float att[NS * 64];    // logits -> attn

    int t = threadIdx.x;
    int b = blockIdx.x >> 3;
    int chunk = blockIdx.x & 7;
    int s = t >> 6, h = t & 63;

    qs[t] = g_q[b * 384 + t];
    __syncthreads();
    float qreg[SD];
#pragma unroll
    for (int d = 0; d < SD; d++) qreg[d] = qs[s * SD + d];

    float accU = 0.f;
    float sred[NS];
#pragma unroll
    for (int ss = 0; ss < NS; ss++) sred[ss] = 0.f;

    for (int tile = 0; tile < 8; tile++) {
        int n0 = chunk * 512 + tile * 64;
        unsigned base = ((unsigned)b * NN + n0) * SD;
        for (int i = t; i < 64 * SD; i += 384) {
            int nn = i >> 6, dd = i & 63;
            kT[dd * 65 + nn] = g_k[base + i];
            vs[i] = g_v[base + i];
        }
        __syncthreads();

        // logits: thread (s, nl=h)
        float l = 0.f;
#pragma unroll
        for (int d = 0; d < SD; d++) l += qreg[d] * kT[d * 65 + h];
        att[s * 64 + h] = l * 0.125f;   // scale = 64^-0.5
        __syncthreads();

        // softmax over slot dim (6), per point
        if (t < 64) {
            float lv[NS];
            float m = -1e30f;
#pragma unroll
            for (int ss = 0; ss < NS; ss++) { lv[ss] = att[ss * 64 + t]; m = fmaxf(m, lv[ss]); }
            float den = 0.f;
#pragma unroll
            for (int ss = 0; ss < NS; ss++) { lv[ss] = expf(lv[ss] - m); den += lv[ss]; }
            float inv = 1.f / den;
#pragma unroll
            for (int ss = 0; ss < NS; ss++) {
                float av = lv[ss] * inv;
                att[ss * 64 + t] = av;
                sred[ss] += av;
            }
        }
        __syncthreads();

        // update accumulation: U[s][h] += sum_nl a[s][nl] * v[nl][h]
        float acc = 0.f;
#pragma unroll
        for (int nl = 0; nl < 64; nl++) acc += att[s * 64 + nl] * vs[nl * SD + h];
        accU += acc;
        __syncthreads();
    }

    g_pU[(((unsigned)b * NCHUNK + chunk) * NS + s) * SD + h] = accU;

    // deterministic per-slot-sum reduction (reuse vs)
    if (t < 64) {
#pragma unroll
        for (int ss = 0; ss < NS; ss++) vs[ss * 64 + t] = sred[ss];
    }
    __syncthreads();
    if (t < NS) {
        float ssum = 0.f;
#pragma unroll
        for (int j = 0; j < 64; j++) ssum += vs[t * 64 + j];
        g_pS[((unsigned)b * NCHUNK + chunk) * NS + t] = ssum;
    }
}

// ---------------- kernel 4: combine + GRU + MLP + LN + q (one batch per block) ----------------
__global__ __launch_bounds__(384) void update_kernel(const float* __restrict__ b_ih,
                                                     const float* __restrict__ b_hh,
                                                     const float* __restrict__ ln_mlp_g,
                                                     const float* __restrict__ ln_mlp_b,
                                                     const float* __restrict__ ln_slot_g,
                                                     const float* __restrict__ ln_slot_b,
                                                     const float* __restrict__ mlp_b1,
                                                     const float* __restrict__ mlp_b2,
                                                     float* __restrict__ out, int last) {
    __shared__ float S[NS];
    __shared__ float prev[NS * SD];
    __shared__ float upd[NS * SD];
    __shared__ float gi[NS * 192];
    __shared__ float gh[NS * 192];
    __shared__ float mln[NS * SD];
    __shared__ float m1[NS * 128];
    __shared__ float red[12][2];

    int b = blockIdx.x;
    int t = threadIdx.x;
    int s = t >> 6, h = t & 63;
    int wid = t >> 5, lane = t & 31;

    // combine partials (fixed order -> deterministic)
    float u = 0.f;
#pragma unroll
    for (int c = 0; c < NCHUNK; c++)
        u += g_pU[(((unsigned)b * NCHUNK + c) * NS + s) * SD + h];
    if (h == 0) {
        float ss = 0.f;
#pragma unroll
        for (int c = 0; c < NCHUNK; c++) ss += g_pS[((unsigned)b * NCHUNK + c) * NS + s];
        S[s] = ss;
    }
    prev[t] = g_slots[b * 384 + t];
    __syncthreads();
    upd[t] = u / (S[s] + 1e-8f);
    __syncthreads();

    // GRU gate matmuls: 2304 length-64 dots, 6 per thread
#pragma unroll
    for (int g = 0; g < 6; g++) {
        int idx = t + g * 384;
        int half = idx / 1152;
        int r = idx - half * 1152;
        int s2 = r / 192, c = r - s2 * 192;
        const float* src = half ? prev : upd;
        const float* wT = half ? g_WhhT : g_WihT;
        float acc = half ? b_hh[c] : b_ih[c];
#pragma unroll
        for (int hh = 0; hh < SD; hh++) acc += src[s2 * SD + hh] * wT[hh * 192 + c];
        if (half) gh[s2 * 192 + c] = acc; else gi[s2 * 192 + c] = acc;
    }
    __syncthreads();

    // gates
    float ir = gi[s * 192 + h], iz = gi[s * 192 + 64 + h], inn = gi[s * 192 + 128 + h];
    float hr = gh[s * 192 + h], hz = gh[s * 192 + 64 + h], hn = gh[s * 192 + 128 + h];
    float rg = 1.f / (1.f + expf(-(ir + hr)));
    float zg = 1.f / (1.f + expf(-(iz + hz)));
    float ng = tanhf(inn + rg * hn);
    float hv = (1.f - zg) * ng + zg * prev[t];

    // LN(hv) with ln_mlp params
    {
        float sum = hv, sq = hv * hv;
        warp_red2(sum, sq);
        if (lane == 0) { red[wid][0] = sum; red[wid][1] = sq; }
    }
    __syncthreads();
    {
        float tsum = red[2 * s][0] + red[2 * s + 1][0];
        float tsq = red[2 * s][1] + red[2 * s + 1][1];
        float m = tsum * (1.f / 64.f);
        float var = tsq * (1.f / 64.f) - m * m;
        float rstd = rsqrtf(var + 1e-5f);
        mln[t] = (hv - m) * rstd * ln_mlp_g[h] + ln_mlp_b[h];
    }
    __syncthreads();

    // MLP layer 1: 768 dots, 2 per thread
#pragma unroll
    for (int g = 0; g < 2; g++) {
        int idx = t + g * 384;
        int s2 = idx >> 7, c = idx & 127;
        float acc = mlp_b1[c];
#pragma unroll
        for (int hh = 0; hh < SD; hh++) acc += mln[s2 * SD + hh] * g_W1T[hh * 128 + c];
        m1[s2 * 128 + c] = fmaxf(acc, 0.f);
    }
    __syncthreads();

    // MLP layer 2 + residual
    float acc2 = mlp_b2[h];
#pragma unroll
    for (int c = 0; c < 128; c++) acc2 += m1[s * 128 + c] * g_W2T[c * SD + h];
    float snew = hv + acc2;
    g_slots[b * 384 + t] = snew;
    if (last) {
        out[b * 384 + t] = snew;
    } else {
        // q for next iteration: LN(snew) with ln_slot params, then Wq
        __syncthreads();
        {
            float sum = snew, sq = snew * snew;
            warp_red2(sum, sq);
            if (lane == 0) { red[wid][0] = sum; red[wid][1] = sq; }
        }
        __syncthreads();
        {
            float tsum = red[2 * s][0] + red[2 * s + 1][0];
            float tsq = red[2 * s][1] + red[2 * s + 1][1];
            float m = tsum * (1.f / 64.f);
            float var = tsq * (1.f / 64.f) - m * m;
            float rstd = rsqrtf(var + 1e-5f);
            mln[t] = (snew - m) * rstd * ln_slot_g[h] + ln_slot_b[h];
        }
        __syncthreads();
        float qv = 0.f;
#pragma unroll
        for (int hh = 0; hh < SD; hh++) qv += mln[s * SD + hh] * g_WqT[hh * SD + h];
        g_q[b * 384 + t] = qv;
    }
}

// ---------------- launch ----------------
extern "C" void kernel_launch(void* const* d_in, const int* in_sizes, int n_in,
                              void* d_out, int out_size) {
    const float* features   = (const float*)d_in[0];
    const float* slot_noise = (const float*)d_in[1];
    const float* slot_mu    = (const float*)d_in[2];
    const float* slot_sigma = (const float*)d_in[3];
    const float* ln_feat_g  = (const float*)d_in[4];
    const float* ln_feat_b  = (const float*)d_in[5];
    const float* ln_slot_g  = (const float*)d_in[6];
    const float* ln_slot_b  = (const float*)d_in[7];
    const float* ln_mlp_g   = (const float*)d_in[8];
    const float* ln_mlp_b   = (const float*)d_in[9];
    const float* Wk         = (const float*)d_in[10];
    const float* Wv         = (const float*)d_in[11];
    const float* Wq         = (const float*)d_in[12];
    const float* W_ih       = (const float*)d_in[13];
    const float* W_hh       = (const float*)d_in[14];
    const float* b_ih       = (const float*)d_in[15];
    const float* b_hh       = (const float*)d_in[16];
    const float* mlp_W1     = (const float*)d_in[17];
    const float* mlp_b1     = (const float*)d_in[18];
    const float* mlp_W2     = (const float*)d_in[19];
    const float* mlp_b2     = (const float*)d_in[20];
    float* out = (float*)d_out;

    const size_t PROJ_SMEM = (size_t)(FEAT * PJ_STRIDE + 32 * 128 + 256 + 256 + 256) * sizeof(float);
    cudaFuncSetAttribute(proj_kernel, cudaFuncAttributeMaxDynamicSharedMemorySize, (int)PROJ_SMEM);

    transpose_kernel<<<64, 256>>>(Wk, Wv, Wq, W_ih, W_hh, mlp_W1, mlp_W2);
    init_kernel<<<BB, 384>>>(slot_noise, slot_mu, slot_sigma, ln_slot_g, ln_slot_b);
    proj_kernel<<<2048, 256, PROJ_SMEM>>>(features, ln_feat_g, ln_feat_b);
    for (int it = 0; it < 3; it++) {
        attn_kernel<<<BB * NCHUNK, 384>>>();
        update_kernel<<<BB, 384>>>(b_ih, b_hh, ln_mlp_g, ln_mlp_b, ln_slot_g, ln_slot_b,
                                   mlp_b1, mlp_b2, out, it == 2);
    }
}

// round 4
// speedup vs baseline: 1.7409x; 1.7409x over previous
#include <cuda_runtime.h>
#include <cuda_bf16.h>
#include <math.h>
#include <stdint.h>

#define BB 64
#define NN 4096
#define FEAT 256
#define NS 6
#define SD 64
#define NCHUNK 8

// ---------------- scratch (device globals: no allocs allowed) ----------------
__device__ float g_k[BB * NN * SD];          // 64 MB
__device__ float g_v[BB * NN * SD];          // 64 MB
__device__ __nv_bfloat16 g_Whi[128 * 256];   // W hi  [n][k]  (n<64: Wk row n, else Wv)
__device__ __nv_bfloat16 g_Wlo[128 * 256];   // W lo  [n][k]
__device__ float g_WqT[SD * SD];             // [h][g]
__device__ float g_WihT[SD * 192];           // [h][c]
__device__ float g_WhhT[SD * 192];           // [h][c]
__device__ float g_W1T[SD * 128];            // [h][c]
__device__ float g_W2T[128 * SD];            // [c][h]
__device__ float g_slots[BB * NS * SD];
__device__ float g_q[BB * NS * SD];
__device__ float g_pU[BB * NCHUNK * NS * SD];
__device__ float g_pS[BB * NCHUNK * NS];

__device__ __forceinline__ void warp_red2(float& a, float& b) {
#pragma unroll
    for (int o = 16; o; o >>= 1) {
        a += __shfl_xor_sync(0xffffffffu, a, o);
        b += __shfl_xor_sync(0xffffffffu, b, o);
    }
}

__device__ __forceinline__ uint32_t smem_u32(const void* p) {
    uint32_t a;
    asm("{ .reg .u64 t; cvta.to.shared.u64 t, %1; cvt.u32.u64 %0, t; }" : "=r"(a) : "l"(p));
    return a;
}

__device__ __forceinline__ void ldsm_x4(uint32_t* r, uint32_t addr) {
    asm volatile("ldmatrix.sync.aligned.m8n8.x4.shared.b16 {%0,%1,%2,%3}, [%4];"
                 : "=r"(r[0]), "=r"(r[1]), "=r"(r[2]), "=r"(r[3]) : "r"(addr));
}

__device__ __forceinline__ void mma_bf16(float* c, const uint32_t* a, uint32_t b0, uint32_t b1) {
    asm volatile(
        "mma.sync.aligned.m16n8k16.row.col.f32.bf16.bf16.f32 "
        "{%0,%1,%2,%3}, {%4,%5,%6,%7}, {%8,%9}, {%0,%1,%2,%3};"
        : "+f"(c[0]), "+f"(c[1]), "+f"(c[2]), "+f"(c[3])
        : "r"(a[0]), "r"(a[1]), "r"(a[2]), "r"(a[3]), "r"(b0), "r"(b1));
}

// ---------------- kernel 0: stage weights (split W to bf16 hi/lo; transpose small mats) ----------------
__global__ void transpose_kernel(const float* __restrict__ Wk, const float* __restrict__ Wv,
                                 const float* __restrict__ Wq, const float* __restrict__ Wih,
                                 const float* __restrict__ Whh, const float* __restrict__ W1,
                                 const float* __restrict__ W2) {
    int tid = blockIdx.x * 256 + threadIdx.x;
    const int stride = 64 * 256;
    for (int idx = tid; idx < 128 * 256; idx += stride) {
        int n = idx >> 8, k = idx & 255;
        float w = (n < 64) ? Wk[n * FEAT + k] : Wv[(n - 64) * FEAT + k];
        __nv_bfloat16 hi = __float2bfloat16(w);
        __nv_bfloat16 lo = __float2bfloat16(w - __bfloat162float(hi));
        g_Whi[idx] = hi;
        g_Wlo[idx] = lo;
    }
    for (int idx = tid; idx < SD * SD; idx += stride) {
        int h = idx >> 6, g = idx & 63;
        g_WqT[idx] = Wq[g * SD + h];
    }
    for (int idx = tid; idx < SD * 192; idx += stride) {
        int h = idx / 192, c = idx % 192;
        g_WihT[idx] = Wih[c * SD + h];
        g_WhhT[idx] = Whh[c * SD + h];
    }
    for (int idx = tid; idx < SD * 128; idx += stride) {
        int h = idx >> 7, c = idx & 127;
        g_W1T[idx] = W1[c * SD + h];
    }
    for (int idx = tid; idx < 128 * SD; idx += stride) {
        int c = idx >> 6, h = idx & 63;
        g_W2T[idx] = W2[h * 128 + c];
    }
}

// ---------------- kernel 1: slots init + q0 ----------------
__global__ __launch_bounds__(384) void init_kernel(const float* __restrict__ noise,
                                                   const float* __restrict__ mu,
                                                   const float* __restrict__ sigma,
                                                   const float* __restrict__ lng,
                                                   const float* __restrict__ lnb) {
    __shared__ float sln[NS * SD];
    __shared__ float red[12][2];
    int b = blockIdx.x;
    int t = threadIdx.x;
    int s = t >> 6, h = t & 63;
    int wid = t >> 5, lane = t & 31;

    float sv = mu[h] + sigma[h] * noise[b * 384 + t];
    g_slots[b * 384 + t] = sv;

    float sum = sv, sq = sv * sv;
    warp_red2(sum, sq);
    if (lane == 0) { red[wid][0] = sum; red[wid][1] = sq; }
    __syncthreads();
    float tsum = red[2 * s][0] + red[2 * s + 1][0];
    float tsq = red[2 * s][1] + red[2 * s + 1][1];
    float m = tsum * (1.f / 64.f);
    float var = tsq * (1.f / 64.f) - m * m;
    float rstd = rsqrtf(var + 1e-5f);
    sln[t] = (sv - m) * rstd * lng[h] + lnb[h];
    __syncthreads();
    float qv = 0.f;
#pragma unroll
    for (int hh = 0; hh < SD; hh++) qv += sln[s * SD + hh] * g_WqT[hh * SD + h];
    g_q[b * 384 + t] = qv;
}

// ---------------- kernel 2: fused LN + K/V projection via HMMA bf16 3-term split ----------------
// smem layout (bytes)
#define OFF_MEAN 0
#define OFF_RSTD 512
#define OFF_SG   1024
#define OFF_SB   2048
#define OFF_AHI  3072
#define A_BYTES  (128 * 272)           // [128 rows][136 bf16] (stride 272B)
#define OFF_ALO  (OFF_AHI + A_BYTES)
#define OFF_BHI  (OFF_ALO + A_BYTES)
#define OFF_BLO  (OFF_BHI + A_BYTES)
#define PROJ_SMEM (OFF_BLO + A_BYTES)  // 142336 B

__global__ __launch_bounds__(256) void proj_mma_kernel(const float* __restrict__ feat,
                                                       const float* __restrict__ lg,
                                                       const float* __restrict__ lb) {
    extern __shared__ char smem[];
    uint32_t sbase = smem_u32(smem);
    int t = threadIdx.x, wid = t >> 5, lane = t & 31;
    int wm = wid >> 2, wn = wid & 3;   // warp grid 2(M) x 4(N); warp tile 64x32
    float* meanp = (float*)(smem + OFF_MEAN);
    float* rstdp = (float*)(smem + OFF_RSTD);
    float* sg = (float*)(smem + OFF_SG);
    float* sbb = (float*)(smem + OFF_SB);

    sg[t] = lg[t];
    sbb[t] = lb[t];

    const float* tileA = feat + (size_t)blockIdx.x * 128 * FEAT;

    // LN stats: warp w handles rows w*16 .. w*16+15
    for (int i = 0; i < 16; i++) {
        int row = wid * 16 + i;
        float4 a = *(const float4*)(tileA + row * FEAT + lane * 4);
        float4 c = *(const float4*)(tileA + row * FEAT + 128 + lane * 4);
        float sum = a.x + a.y + a.z + a.w + c.x + c.y + c.z + c.w;
        float sq = a.x * a.x + a.y * a.y + a.z * a.z + a.w * a.w +
                   c.x * c.x + c.y * c.y + c.z * c.z + c.w * c.w;
        warp_red2(sum, sq);
        if (lane == 0) {
            float m = sum * (1.f / 256.f);
            float var = sq * (1.f / 256.f) - m * m;
            meanp[row] = m;
            rstdp[row] = rsqrtf(var + 1e-5f);
        }
    }

    float acc[4][4][4];
#pragma unroll
    for (int a = 0; a < 4; a++)
#pragma unroll
        for (int b = 0; b < 4; b++)
#pragma unroll
            for (int c = 0; c < 4; c++) acc[a][b][c] = 0.f;

    for (int kc = 0; kc < 2; kc++) {
        __syncthreads();
        // normalize + split A chunk into sA_hi / sA_lo
        for (int i = t; i < 4096; i += 256) {
            int row = i >> 5;
            int k4 = (i & 31) * 4;
            int kg = kc * 128 + k4;
            float4 x = *(const float4*)(tileA + row * FEAT + kg);
            float m = meanp[row], r = rstdp[row];
            float4 gg = *(const float4*)(sg + kg);
            float4 bbv = *(const float4*)(sbb + kg);
            x.x = (x.x - m) * r * gg.x + bbv.x;
            x.y = (x.y - m) * r * gg.y + bbv.y;
            x.z = (x.z - m) * r * gg.z + bbv.z;
            x.w = (x.w - m) * r * gg.w + bbv.w;
            __nv_bfloat16 h0 = __float2bfloat16(x.x), h1 = __float2bfloat16(x.y);
            __nv_bfloat16 h2 = __float2bfloat16(x.z), h3 = __float2bfloat16(x.w);
            __nv_bfloat16 l0 = __float2bfloat16(x.x - __bfloat162float(h0));
            __nv_bfloat16 l1 = __float2bfloat16(x.y - __bfloat162float(h1));
            __nv_bfloat16 l2 = __float2bfloat16(x.z - __bfloat162float(h2));
            __nv_bfloat16 l3 = __float2bfloat16(x.w - __bfloat162float(h3));
            uint2 hw, lw;
            hw.x = (uint32_t)__bfloat16_as_ushort(h0) | ((uint32_t)__bfloat16_as_ushort(h1) << 16);
            hw.y = (uint32_t)__bfloat16_as_ushort(h2) | ((uint32_t)__bfloat16_as_ushort(h3) << 16);
            lw.x = (uint32_t)__bfloat16_as_ushort(l0) | ((uint32_t)__bfloat16_as_ushort(l1) << 16);
            lw.y = (uint32_t)__bfloat16_as_ushort(l2) | ((uint32_t)__bfloat16_as_ushort(l3) << 16);
            unsigned off = (unsigned)row * 272u + (unsigned)k4 * 2u;
            *(uint2*)(smem + OFF_AHI + off) = hw;
            *(uint2*)(smem + OFF_ALO + off) = lw;
        }
        // copy B chunk (bf16 hi/lo, [n][k] rows of 128 bf16 = 16B x 16)
        for (int i = t; i < 2048; i += 256) {
            int n = i >> 4, j = i & 15;
            unsigned so = (unsigned)n * 272u + (unsigned)j * 16u;
            *(uint4*)(smem + OFF_BHI + so) = *(const uint4*)(g_Whi + n * 256 + kc * 128 + j * 8);
            *(uint4*)(smem + OFF_BLO + so) = *(const uint4*)(g_Wlo + n * 256 + kc * 128 + j * 8);
        }
        __syncthreads();

        // A frag addressing: lanes 0-15 rows base+(lane&15) khalf0; 16-31 khalf1
        int arow = wm * 64 + (lane & 15);
        int akh = (lane >> 4) * 8;
        // B frag addressing: g=lane>>3: row = n0 + (g>>1)*8 + (lane&7), khalf = (g&1)*8
        int bg = lane >> 3;
        int brow = wn * 32 + ((bg >> 1) * 8) + (lane & 7);
        int bkh = (bg & 1) * 8;

#pragma unroll
        for (int ks = 0; ks < 8; ks++) {
            int kb = ks * 16;
            uint32_t ah[4][4], al[4][4], bh[2][4], bl[2][4];
#pragma unroll
            for (int mi = 0; mi < 4; mi++) {
                uint32_t ao = sbase + (uint32_t)((arow + mi * 16) * 272 + (kb + akh) * 2);
                ldsm_x4(ah[mi], ao + OFF_AHI);
                ldsm_x4(al[mi], ao + OFF_ALO);
            }
#pragma unroll
            for (int p = 0; p < 2; p++) {
                uint32_t bo = sbase + (uint32_t)((brow + p * 16) * 272 + (kb + bkh) * 2);
                ldsm_x4(bh[p], bo + OFF_BHI);
                ldsm_x4(bl[p], bo + OFF_BLO);
            }
#pragma unroll
            for (int mi = 0; mi < 4; mi++)
#pragma unroll
                for (int ni = 0; ni < 4; ni++) {
                    int p = ni >> 1, rp = (ni & 1) * 2;
                    mma_bf16(acc[mi][ni], ah[mi], bh[p][rp], bh[p][rp + 1]);
                    mma_bf16(acc[mi][ni], ah[mi], bl[p][rp], bl[p][rp + 1]);
                    mma_bf16(acc[mi][ni], al[mi], bh[p][rp], bh[p][rp + 1]);
                }
        }
    }

    // epilogue: write k (wn 0-1) / v (wn 2-3)
    int qr = lane >> 2, qc = lane & 3;
    unsigned rbase = blockIdx.x * 128u + wm * 64;
#pragma unroll
    for (int mi = 0; mi < 4; mi++)
#pragma unroll
        for (int ni = 0; ni < 4; ni++) {
            int n = wn * 32 + ni * 8 + 2 * qc;
            float* dst = (n < 64) ? g_k : g_v;
            int nn = n & 63;
            unsigned r0 = rbase + mi * 16 + qr;
            *(float2*)(dst + (size_t)r0 * SD + nn) = make_float2(acc[mi][ni][0], acc[mi][ni][1]);
            *(float2*)(dst + (size_t)(r0 + 8) * SD + nn) = make_float2(acc[mi][ni][2], acc[mi][ni][3]);
        }
}

// ---------------- kernel 3: fused attention pass (192 threads, warp = slot) ----------------
__global__ __launch_bounds__(192) void attn_kernel() {
    __shared__ float qs[NS * SD];
    __shared__ float kT[SD * 66];     // [d][n] padded
    __shared__ float vs[64 * SD];     // [n][h]
    __shared__ float att[NS * 64];
    __shared__ float sredb[NS * 64];

    int t = threadIdx.x;
    int b = blockIdx.x >> 3;
    int chunk = blockIdx.x & 7;
    int w = t >> 5, lane = t & 31;

    for (int i = t; i < 384; i += 192) qs[i] = g_q[b * 384 + i];

    float sred[NS] = {0.f, 0.f, 0.f, 0.f, 0.f, 0.f};
    float2 accU = make_float2(0.f, 0.f);
    __syncthreads();

    for (int tile = 0; tile < 8; tile++) {
        size_t base = ((size_t)b * NN + chunk * 512 + tile * 64) * SD;
        for (int i = t; i < 1024; i += 192) {
            int n = i >> 4, q4 = (i & 15) * 4;
            float4 kv = *(const float4*)(g_k + base + n * SD + q4);
            kT[(q4 + 0) * 66 + n] = kv.x;
            kT[(q4 + 1) * 66 + n] = kv.y;
            kT[(q4 + 2) * 66 + n] = kv.z;
            kT[(q4 + 3) * 66 + n] = kv.w;
            *(float4*)(vs + n * SD + q4) = *(const float4*)(g_v + base + n * SD + q4);
        }
        __syncthreads();

        // logits: warp w = slot, lane = n-pair
        {
            float2 l = make_float2(0.f, 0.f);
#pragma unroll
            for (int d = 0; d < SD; d++) {
                float qv = qs[w * SD + d];
                float2 kk = *(const float2*)(kT + d * 66 + 2 * lane);
                l.x += qv * kk.x;
                l.y += qv * kk.y;
            }
            *(float2*)(att + w * 64 + 2 * lane) = make_float2(l.x * 0.125f, l.y * 0.125f);
        }
        __syncthreads();

        // softmax over slot dim per point
        if (t < 64) {
            float lv[NS];
            float mx = -1e30f;
#pragma unroll
            for (int ss = 0; ss < NS; ss++) { lv[ss] = att[ss * 64 + t]; mx = fmaxf(mx, lv[ss]); }
            float den = 0.f;
#pragma unroll
            for (int ss = 0; ss < NS; ss++) { lv[ss] = expf(lv[ss] - mx); den += lv[ss]; }
            float inv = 1.f / den;
#pragma unroll
            for (int ss = 0; ss < NS; ss++) {
                float av = lv[ss] * inv;
                att[ss * 64 + t] = av;
                sred[ss] += av;
            }
        }
        __syncthreads();

        // update: warp w = slot, lane = h-pair
#pragma unroll
        for (int n = 0; n < 64; n++) {
            float a = att[w * 64 + n];
            float2 v2 = *(const float2*)(vs + n * SD + 2 * lane);
            accU.x += a * v2.x;
            accU.y += a * v2.y;
        }
        __syncthreads();
    }

    {
        float* p = g_pU + (((size_t)b * NCHUNK + chunk) * NS + w) * SD + 2 * lane;
        p[0] = accU.x;
        p[1] = accU.y;
    }
    if (t < 64) {
#pragma unroll
        for (int ss = 0; ss < NS; ss++) sredb[ss * 64 + t] = sred[ss];
    }
    __syncthreads();
    if (t < NS) {
        float ssum = 0.f;
#pragma unroll
        for (int j = 0; j < 64; j++) ssum += sredb[t * 64 + j];
        g_pS[((unsigned)b * NCHUNK + chunk) * NS + t] = ssum;
    }
}

// ---------------- kernel 4: combine + GRU + MLP + LN + q (one batch per block) ----------------
__global__ __launch_bounds__(384) void update_kernel(const float* __restrict__ b_ih,
                                                     const float* __restrict__ b_hh,
                                                     const float* __restrict__ ln_mlp_g,
                                                     const float* __restrict__ ln_mlp_b,
                                                     const float* __restrict__ ln_slot_g,
                                                     const float* __restrict__ ln_slot_b,
                                                     const float* __restrict__ mlp_b1,
                                                     const float* __restrict__ mlp_b2,
                                                     float* __restrict__ out, int last) {
    __shared__ float S[NS];
    __shared__ float prev[NS * SD];
    __shared__ float upd[NS * SD];
    __shared__ float gi[NS * 192];
    __shared__ float gh[NS * 192];
    __shared__ float mln[NS * SD];
    __shared__ float m1[NS * 128];
    __shared__ float red[12][2];

    int b = blockIdx.x;
    int t = threadIdx.x;
    int s = t >> 6, h = t & 63;
    int wid = t >> 5, lane = t & 31;

    float u = 0.f;
#pragma unroll
    for (int c = 0; c < NCHUNK; c++)
        u += g_pU[(((unsigned)b * NCHUNK + c) * NS + s) * SD + h];
    if (h == 0) {
        float ss = 0.f;
#pragma unroll
        for (int c = 0; c < NCHUNK; c++) ss += g_pS[((unsigned)b * NCHUNK + c) * NS + s];
        S[s] = ss;
    }
    prev[t] = g_slots[b * 384 + t];
    __syncthreads();
    upd[t] = u / (S[s] + 1e-8f);
    __syncthreads();

#pragma unroll
    for (int g = 0; g < 6; g++) {
        int idx = t + g * 384;
        int half = idx / 1152;
        int r = idx - half * 1152;
        int s2 = r / 192, c = r - s2 * 192;
        const float* src = half ? prev : upd;
        const float* wT = half ? g_WhhT : g_WihT;
        float acc = half ? b_hh[c] : b_ih[c];
#pragma unroll
        for (int hh = 0; hh < SD; hh++) acc += src[s2 * SD + hh] * wT[hh * 192 + c];
        if (half) gh[s2 * 192 + c] = acc; else gi[s2 * 192 + c] = acc;
    }
    __syncthreads();

    float ir = gi[s * 192 + h], iz = gi[s * 192 + 64 + h], inn = gi[s * 192 + 128 + h];
    float hr = gh[s * 192 + h], hz = gh[s * 192 + 64 + h], hn = gh[s * 192 + 128 + h];
    float rg = 1.f / (1.f + expf(-(ir + hr)));
    float zg = 1.f / (1.f + expf(-(iz + hz)));
    float ng = tanhf(inn + rg * hn);
    float hv = (1.f - zg) * ng + zg * prev[t];

    {
        float sum = hv, sq = hv * hv;
        warp_red2(sum, sq);
        if (lane == 0) { red[wid][0] = sum; red[wid][1] = sq; }
    }
    __syncthreads();
    {
        float tsum = red[2 * s][0] + red[2 * s + 1][0];
        float tsq = red[2 * s][1] + red[2 * s + 1][1];
        float m = tsum * (1.f / 64.f);
        float var = tsq * (1.f / 64.f) - m * m;
        float rstd = rsqrtf(var + 1e-5f);
        mln[t] = (hv - m) * rstd * ln_mlp_g[h] + ln_mlp_b[h];
    }
    __syncthreads();

#pragma unroll
    for (int g = 0; g < 2; g++) {
        int idx = t + g * 384;
        int s2 = idx >> 7, c = idx & 127;
        float acc = mlp_b1[c];
#pragma unroll
        for (int hh = 0; hh < SD; hh++) acc += mln[s2 * SD + hh] * g_W1T[hh * 128 + c];
        m1[s2 * 128 + c] = fmaxf(acc, 0.f);
    }
    __syncthreads();

    float acc2 = mlp_b2[h];
#pragma unroll
    for (int c = 0; c < 128; c++) acc2 += m1[s * 128 + c] * g_W2T[c * SD + h];
    float snew = hv + acc2;
    g_slots[b * 384 + t] = snew;
    if (last) {
        out[b * 384 + t] = snew;
    } else {
        __syncthreads();
        {
            float sum = snew, sq = snew * snew;
            warp_red2(sum, sq);
            if (lane == 0) { red[wid][0] = sum; red[wid][1] = sq; }
        }
        __syncthreads();
        {
            float tsum = red[2 * s][0] + red[2 * s + 1][0];
            float tsq = red[2 * s][1] + red[2 * s + 1][1];
            float m = tsum * (1.f / 64.f);
            float var = tsq * (1.f / 64.f) - m * m;
            float rstd = rsqrtf(var + 1e-5f);
            mln[t] = (snew - m) * rstd * ln_slot_g[h] + ln_slot_b[h];
        }
        __syncthreads();
        float qv = 0.f;
#pragma unroll
        for (int hh = 0; hh < SD; hh++) qv += mln[s * SD + hh] * g_WqT[hh * SD + h];
        g_q[b * 384 + t] = qv;
    }
}

// ---------------- launch ----------------
extern "C" void kernel_launch(void* const* d_in, const int* in_sizes, int n_in,
                              void* d_out, int out_size) {
    const float* features   = (const float*)d_in[0];
    const float* slot_noise = (const float*)d_in[1];
    const float* slot_mu    = (const float*)d_in[2];
    const float* slot_sigma = (const float*)d_in[3];
    const float* ln_feat_g  = (const float*)d_in[4];
    const float* ln_feat_b  = (const float*)d_in[5];
    const float* ln_slot_g  = (const float*)d_in[6];
    const float* ln_slot_b  = (const float*)d_in[7];
    const float* ln_mlp_g   = (const float*)d_in[8];
    const float* ln_mlp_b   = (const float*)d_in[9];
    const float* Wk         = (const float*)d_in[10];
    const float* Wv         = (const float*)d_in[11];
    const float* Wq         = (const float*)d_in[12];
    const float* W_ih       = (const float*)d_in[13];
    const float* W_hh       = (const float*)d_in[14];
    const float* b_ih       = (const float*)d_in[15];
    const float* b_hh       = (const float*)d_in[16];
    const float* mlp_W1     = (const float*)d_in[17];
    const float* mlp_b1     = (const float*)d_in[18];
    const float* mlp_W2     = (const float*)d_in[19];
    const float* mlp_b2     = (const float*)d_in[20];
    float* out = (float*)d_out;

    cudaFuncSetAttribute(proj_mma_kernel, cudaFuncAttributeMaxDynamicSharedMemorySize, PROJ_SMEM);

    transpose_kernel<<<64, 256>>>(Wk, Wv, Wq, W_ih, W_hh, mlp_W1, mlp_W2);
    init_kernel<<<BB, 384>>>(slot_noise, slot_mu, slot_sigma, ln_slot_g, ln_slot_b);
    proj_mma_kernel<<<2048, 256, PROJ_SMEM>>>(features, ln_feat_g, ln_feat_b);
    for (int it = 0; it < 3; it++) {
        attn_kernel<<<BB * NCHUNK, 192>>>();
        update_kernel<<<BB, 384>>>(b_ih, b_hh, ln_mlp_g, ln_mlp_b, ln_slot_g, ln_slot_b,
                                   mlp_b1, mlp_b2, out, it == 2);
    }
}

// round 5
// speedup vs baseline: 1.8873x; 1.0841x over previous
#include <cuda_runtime.h>
#include <cuda_bf16.h>
#include <math.h>
#include <stdint.h>

#define BB 64
#define NN 4096
#define FEAT 256
#define NS 6
#define SD 64
#define NCHUNK 8

// ---------------- scratch (device globals: no allocs allowed) ----------------
__device__ float g_kT[BB * SD * NN];         // 64 MB  [b][d][n]
__device__ float g_v[BB * NN * SD];          // 64 MB  [b*n][h]
__device__ __nv_bfloat16 g_Whi[128 * 256];   // (W*g) hi  [n][k]
__device__ __nv_bfloat16 g_Wlo[128 * 256];   // (W*g) lo  [n][k]
__device__ float g_c1[128];                  // W @ ln_feat_b
__device__ float g_c2[128];                  // W @ ln_feat_g
__device__ float g_WqT[SD * SD];
__device__ float g_WihT[SD * 192];
__device__ float g_WhhT[SD * 192];
__device__ float g_W1T[SD * 128];
__device__ float g_W2T[128 * SD];
__device__ float g_slots[BB * NS * SD];
__device__ float g_q[BB * NS * SD];
__device__ float g_pU[BB * NCHUNK * NS * SD];
__device__ float g_pS[BB * NCHUNK * NS];

__device__ __forceinline__ void warp_red2(float& a, float& b) {
#pragma unroll
    for (int o = 16; o; o >>= 1) {
        a += __shfl_xor_sync(0xffffffffu, a, o);
        b += __shfl_xor_sync(0xffffffffu, b, o);
    }
}

__device__ __forceinline__ uint32_t smem_u32(const void* p) {
    uint32_t a;
    asm("{ .reg .u64 t; cvta.to.shared.u64 t, %1; cvt.u32.u64 %0, t; }" : "=r"(a) : "l"(p));
    return a;
}

__device__ __forceinline__ void ldsm_x4(uint32_t* r, uint32_t addr) {
    asm volatile("ldmatrix.sync.aligned.m8n8.x4.shared.b16 {%0,%1,%2,%3}, [%4];"
                 : "=r"(r[0]), "=r"(r[1]), "=r"(r[2]), "=r"(r[3]) : "r"(addr));
}

__device__ __forceinline__ void mma_bf16(float* c, const uint32_t* a, uint32_t b0, uint32_t b1) {
    asm volatile(
        "mma.sync.aligned.m16n8k16.row.col.f32.bf16.bf16.f32 "
        "{%0,%1,%2,%3}, {%4,%5,%6,%7}, {%8,%9}, {%0,%1,%2,%3};"
        : "+f"(c[0]), "+f"(c[1]), "+f"(c[2]), "+f"(c[3])
        : "r"(a[0]), "r"(a[1]), "r"(a[2]), "r"(a[3]), "r"(b0), "r"(b1));
}

// ---------------- kernel 0: stage weights ----------------
__global__ void transpose_kernel(const float* __restrict__ Wk, const float* __restrict__ Wv,
                                 const float* __restrict__ Wq, const float* __restrict__ Wih,
                                 const float* __restrict__ Whh, const float* __restrict__ W1,
                                 const float* __restrict__ W2, const float* __restrict__ lfg,
                                 const float* __restrict__ lfb) {
    int tid = blockIdx.x * 256 + threadIdx.x;
    const int stride = 64 * 256;
    for (int idx = tid; idx < 128 * 256; idx += stride) {
        int n = idx >> 8, k = idx & 255;
        float w = ((n < 64) ? Wk[n * FEAT + k] : Wv[(n - 64) * FEAT + k]) * lfg[k];
        __nv_bfloat16 hi = __float2bfloat16(w);
        __nv_bfloat16 lo = __float2bfloat16(w - __bfloat162float(hi));
        g_Whi[idx] = hi;
        g_Wlo[idx] = lo;
    }
    if (blockIdx.x == 0) {
        int t = threadIdx.x;
        int n = t & 127;
        const float* Wr = (n < 64) ? (Wk + n * FEAT) : (Wv + (n - 64) * FEAT);
        const float* vec = (t < 128) ? lfb : lfg;
        float acc = 0.f;
        for (int k = 0; k < 256; k++) acc += Wr[k] * vec[k];
        if (t < 128) g_c1[n] = acc; else g_c2[n] = acc;
    }
    for (int idx = tid; idx < SD * SD; idx += stride) {
        int h = idx >> 6, g = idx & 63;
        g_WqT[idx] = Wq[g * SD + h];
    }
    for (int idx = tid; idx < SD * 192; idx += stride) {
        int h = idx / 192, c = idx % 192;
        g_WihT[idx] = Wih[c * SD + h];
        g_WhhT[idx] = Whh[c * SD + h];
    }
    for (int idx = tid; idx < SD * 128; idx += stride) {
        int h = idx >> 7, c = idx & 127;
        g_W1T[idx] = W1[c * SD + h];
    }
    for (int idx = tid; idx < 128 * SD; idx += stride) {
        int c = idx >> 6, h = idx & 63;
        g_W2T[idx] = W2[h * 128 + c];
    }
}

// ---------------- kernel 1: slots init + q0 ----------------
__global__ __launch_bounds__(384) void init_kernel(const float* __restrict__ noise,
                                                   const float* __restrict__ mu,
                                                   const float* __restrict__ sigma,
                                                   const float* __restrict__ lng,
                                                   const float* __restrict__ lnb) {
    __shared__ float sln[NS * SD];
    __shared__ float red[12][2];
    int b = blockIdx.x;
    int t = threadIdx.x;
    int s = t >> 6, h = t & 63;
    int wid = t >> 5, lane = t & 31;

    float sv = mu[h] + sigma[h] * noise[b * 384 + t];
    g_slots[b * 384 + t] = sv;

    float sum = sv, sq = sv * sv;
    warp_red2(sum, sq);
    if (lane == 0) { red[wid][0] = sum; red[wid][1] = sq; }
    __syncthreads();
    float tsum = red[2 * s][0] + red[2 * s + 1][0];
    float tsq = red[2 * s][1] + red[2 * s + 1][1];
    float m = tsum * (1.f / 64.f);
    float var = tsq * (1.f / 64.f) - m * m;
    float rstd = rsqrtf(var + 1e-5f);
    sln[t] = (sv - m) * rstd * lng[h] + lnb[h];
    __syncthreads();
    float qv = 0.f;
#pragma unroll
    for (int hh = 0; hh < SD; hh++) qv += sln[s * SD + hh] * g_WqT[hh * SD + h];
    g_q[b * 384 + t] = qv;
}

// ---------------- kernel 2: K/V projection (raw X GEMM + LN epilogue fold) ----------------
#define PA_STRIDE 528               // bytes per A row (256 bf16 + 8 pad)
#define PB_STRIDE 272               // bytes per B row (128 bf16 + 8 pad)
#define OFF_MR  0                   // [128][2] floats (m, r)
#define OFF_C1  1024
#define OFF_C2  1536
#define OFF_AHI 2048
#define A_BYTES (128 * PA_STRIDE)   // 67584
#define OFF_ALO (OFF_AHI + A_BYTES)
#define OFF_BHI (OFF_ALO + A_BYTES)
#define B_BYTES (128 * PB_STRIDE)   // 34816
#define OFF_BLO (OFF_BHI + B_BYTES)
#define PROJ_SMEM (OFF_BLO + B_BYTES)   // 206848

__global__ __launch_bounds__(512) void proj_mma_kernel(const float* __restrict__ feat) {
    extern __shared__ char smem[];
    uint32_t sbase = smem_u32(smem);
    int t = threadIdx.x, wid = t >> 5, lane = t & 31;
    int wm = wid >> 2, wn = wid & 3;   // warp grid 4(M) x 4(N); warp tile 32x32
    float* mr = (float*)(smem + OFF_MR);
    float* c1s = (float*)(smem + OFF_C1);
    float* c2s = (float*)(smem + OFF_C2);

    if (t < 128) { c1s[t] = g_c1[t]; c2s[t] = g_c2[t]; }

    const float* tileA = feat + (size_t)blockIdx.x * 128 * FEAT;

    // single pass: load raw X, stats + hi/lo split together. warp w: rows w*8..w*8+7
    for (int i = 0; i < 8; i++) {
        int row = wid * 8 + i;
        float4 a = *(const float4*)(tileA + row * FEAT + lane * 4);
        float4 c = *(const float4*)(tileA + row * FEAT + 128 + lane * 4);
        float sum = a.x + a.y + a.z + a.w + c.x + c.y + c.z + c.w;
        float sq = a.x * a.x + a.y * a.y + a.z * a.z + a.w * a.w +
                   c.x * c.x + c.y * c.y + c.z * c.z + c.w * c.w;
        // split both float4s into bf16 hi/lo
#pragma unroll
        for (int hseg = 0; hseg < 2; hseg++) {
            float4 x = hseg ? c : a;
            __nv_bfloat16 h0 = __float2bfloat16(x.x), h1 = __float2bfloat16(x.y);
            __nv_bfloat16 h2 = __float2bfloat16(x.z), h3 = __float2bfloat16(x.w);
            __nv_bfloat16 l0 = __float2bfloat16(x.x - __bfloat162float(h0));
            __nv_bfloat16 l1 = __float2bfloat16(x.y - __bfloat162float(h1));
            __nv_bfloat16 l2 = __float2bfloat16(x.z - __bfloat162float(h2));
            __nv_bfloat16 l3 = __float2bfloat16(x.w - __bfloat162float(h3));
            uint2 hw, lw;
            hw.x = (uint32_t)__bfloat16_as_ushort(h0) | ((uint32_t)__bfloat16_as_ushort(h1) << 16);
            hw.y = (uint32_t)__bfloat16_as_ushort(h2) | ((uint32_t)__bfloat16_as_ushort(h3) << 16);
            lw.x = (uint32_t)__bfloat16_as_ushort(l0) | ((uint32_t)__bfloat16_as_ushort(l1) << 16);
            lw.y = (uint32_t)__bfloat16_as_ushort(l2) | ((uint32_t)__bfloat16_as_ushort(l3) << 16);
            unsigned off = (unsigned)row * PA_STRIDE + (unsigned)(hseg * 128 + lane * 4) * 2u;
            *(uint2*)(smem + OFF_AHI + off) = hw;
            *(uint2*)(smem + OFF_ALO + off) = lw;
        }
        warp_red2(sum, sq);
        if (lane == 0) {
            float m = sum * (1.f / 256.f);
            float var = sq * (1.f / 256.f) - m * m;
            mr[row * 2] = m;
            mr[row * 2 + 1] = rsqrtf(var + 1e-5f);
        }
    }

    float acc[2][4][4];
#pragma unroll
    for (int a = 0; a < 2; a++)
#pragma unroll
        for (int b = 0; b < 4; b++)
#pragma unroll
            for (int c = 0; c < 4; c++) acc[a][b][c] = 0.f;

    int arow = wm * 32 + (lane & 15);
    int akh = (lane >> 4) * 8;
    int bg = lane >> 3;
    int brow = wn * 32 + ((bg >> 1) * 8) + (lane & 7);
    int bkh = (bg & 1) * 8;

    for (int kc = 0; kc < 2; kc++) {
        __syncthreads();
        // copy B chunk (hi/lo)
        for (int i = t; i < 2048; i += 512) {
            int n = i >> 4, j = i & 15;
            unsigned so = (unsigned)n * PB_STRIDE + (unsigned)j * 16u;
            *(uint4*)(smem + OFF_BHI + so) = *(const uint4*)(g_Whi + n * 256 + kc * 128 + j * 8);
            *(uint4*)(smem + OFF_BLO + so) = *(const uint4*)(g_Wlo + n * 256 + kc * 128 + j * 8);
        }
        __syncthreads();

#pragma unroll
        for (int ks = 0; ks < 8; ks++) {
            int kb = ks * 16;
            uint32_t ah[2][4], al[2][4], bh[2][4], bl[2][4];
#pragma unroll
            for (int mi = 0; mi < 2; mi++) {
                uint32_t ao = sbase + (uint32_t)((arow + mi * 16) * PA_STRIDE +
                                                 (kc * 128 + kb + akh) * 2);
                ldsm_x4(ah[mi], ao + OFF_AHI);
                ldsm_x4(al[mi], ao + OFF_ALO);
            }
#pragma unroll
            for (int p = 0; p < 2; p++) {
                uint32_t bo = sbase + (uint32_t)((brow + p * 16) * PB_STRIDE + (kb + bkh) * 2);
                ldsm_x4(bh[p], bo + OFF_BHI);
                ldsm_x4(bl[p], bo + OFF_BLO);
            }
#pragma unroll
            for (int mi = 0; mi < 2; mi++)
#pragma unroll
                for (int ni = 0; ni < 4; ni++) {
                    int p = ni >> 1, rp = (ni & 1) * 2;
                    mma_bf16(acc[mi][ni], ah[mi], bh[p][rp], bh[p][rp + 1]);
                    mma_bf16(acc[mi][ni], ah[mi], bl[p][rp], bl[p][rp + 1]);
                    mma_bf16(acc[mi][ni], al[mi], bh[p][rp], bh[p][rp + 1]);
                }
        }
    }

    // epilogue: out = r*p + c1[n] - m*r*c2[n]; n<64 -> g_kT[b][d][n], else g_v
    int qr = lane >> 2, qc = lane & 3;
#pragma unroll
    for (int mi = 0; mi < 2; mi++) {
        int lrow = wm * 32 + mi * 16 + qr;
        float m0 = mr[lrow * 2], r0 = mr[lrow * 2 + 1];
        float m1 = mr[(lrow + 8) * 2], r1 = mr[(lrow + 8) * 2 + 1];
        unsigned g0 = blockIdx.x * 128u + lrow;
        unsigned g1 = g0 + 8;
        unsigned bidx = g0 >> 12;
        unsigned np0 = g0 & 4095u, np1 = g1 & 4095u;
#pragma unroll
        for (int ni = 0; ni < 4; ni++) {
            int n = wn * 32 + ni * 8 + 2 * qc;
            float C1a = c1s[n], C2a = c2s[n], C1b = c1s[n + 1], C2b = c2s[n + 1];
            float v00 = fmaf(r0, acc[mi][ni][0], fmaf(-m0 * r0, C2a, C1a));
            float v01 = fmaf(r0, acc[mi][ni][1], fmaf(-m0 * r0, C2b, C1b));
            float v10 = fmaf(r1, acc[mi][ni][2], fmaf(-m1 * r1, C2a, C1a));
            float v11 = fmaf(r1, acc[mi][ni][3], fmaf(-m1 * r1, C2b, C1b));
            if (n < 64) {
                float* kb0 = g_kT + (size_t)bidx * (SD * NN) + (size_t)n * NN;
                kb0[np0] = v00;
                kb0[np1] = v10;
                kb0[NN + np0] = v01;
                kb0[NN + np1] = v11;
            } else {
                int hh = n - 64;
                *(float2*)(g_v + (size_t)g0 * SD + hh) = make_float2(v00, v01);
                *(float2*)(g_v + (size_t)g1 * SD + hh) = make_float2(v10, v11);
            }
        }
    }
}

// ---------------- kernel 3: fused attention pass (192 threads, warp = slot) ----------------
__global__ __launch_bounds__(192) void attn_kernel() {
    __shared__ float qs[NS * SD];
    __shared__ float kts[64 * 64];    // [d][n]
    __shared__ float vs[64 * SD];     // [n][h]
    __shared__ float att[NS * 64];
    __shared__ float sredb[NS * 64];

    int t = threadIdx.x;
    int b = blockIdx.x >> 3;
    int chunk = blockIdx.x & 7;
    int w = t >> 5, lane = t & 31;
    int half = lane >> 4, l16 = lane & 15;

    for (int i = t; i < 384; i += 192) qs[i] = g_q[b * 384 + i];

    float sred[NS] = {0.f, 0.f, 0.f, 0.f, 0.f, 0.f};
    float4 accU = make_float4(0.f, 0.f, 0.f, 0.f);
    __syncthreads();

    const float* kTb = g_kT + (size_t)b * (SD * NN);
    for (int tile = 0; tile < 8; tile++) {
        int n0 = chunk * 512 + tile * 64;
        for (int i = t; i < 1024; i += 192) {
            int d = i >> 4, j = i & 15;
            ((float4*)kts)[i] = *(const float4*)(kTb + (size_t)d * NN + n0 + j * 4);
            ((float4*)vs)[i] = *(const float4*)(g_v + ((size_t)b * NN + n0 + d) * SD + j * 4);
        }
        __syncthreads();

        // logits: warp w = slot; lanes split by d parity, quad of n per lane
        {
            float4 l = make_float4(0.f, 0.f, 0.f, 0.f);
#pragma unroll
            for (int dd = 0; dd < 32; dd++) {
                int d = 2 * dd + half;
                float qv = qs[w * 64 + d];
                float4 kk = *(const float4*)(kts + d * 64 + 4 * l16);
                l.x += qv * kk.x; l.y += qv * kk.y; l.z += qv * kk.z; l.w += qv * kk.w;
            }
            l.x += __shfl_xor_sync(0xffffffffu, l.x, 16);
            l.y += __shfl_xor_sync(0xffffffffu, l.y, 16);
            l.z += __shfl_xor_sync(0xffffffffu, l.z, 16);
            l.w += __shfl_xor_sync(0xffffffffu, l.w, 16);
            if (half == 0)
                *(float4*)(att + w * 64 + 4 * l16) =
                    make_float4(l.x * 0.125f, l.y * 0.125f, l.z * 0.125f, l.w * 0.125f);
        }
        __syncthreads();

        // softmax over slot dim per point
        if (t < 64) {
            float lv[NS];
            float mx = -1e30f;
#pragma unroll
            for (int ss = 0; ss < NS; ss++) { lv[ss] = att[ss * 64 + t]; mx = fmaxf(mx, lv[ss]); }
            float den = 0.f;
#pragma unroll
            for (int ss = 0; ss < NS; ss++) { lv[ss] = expf(lv[ss] - mx); den += lv[ss]; }
            float inv = 1.f / den;
#pragma unroll
            for (int ss = 0; ss < NS; ss++) {
                float av = lv[ss] * inv;
                att[ss * 64 + t] = av;
                sred[ss] += av;
            }
        }
        __syncthreads();

        // update: lanes split by n parity, quad of h per lane
#pragma unroll
        for (int nn = 0; nn < 32; nn++) {
            int n = 2 * nn + half;
            float a = att[w * 64 + n];
            float4 v4 = *(const float4*)(vs + n * 64 + 4 * l16);
            accU.x += a * v4.x; accU.y += a * v4.y; accU.z += a * v4.z; accU.w += a * v4.w;
        }
        __syncthreads();
    }

    accU.x += __shfl_xor_sync(0xffffffffu, accU.x, 16);
    accU.y += __shfl_xor_sync(0xffffffffu, accU.y, 16);
    accU.z += __shfl_xor_sync(0xffffffffu, accU.z, 16);
    accU.w += __shfl_xor_sync(0xffffffffu, accU.w, 16);
    if (half == 0)
        *(float4*)(g_pU + (((size_t)b * NCHUNK + chunk) * NS + w) * SD + 4 * l16) = accU;

    if (t < 64) {
#pragma unroll
        for (int ss = 0; ss < NS; ss++) sredb[ss * 64 + t] = sred[ss];
    }
    __syncthreads();
    if (t < NS) {
        float ssum = 0.f;
#pragma unroll
        for (int j = 0; j < 64; j++) ssum += sredb[t * 64 + j];
        g_pS[((unsigned)b * NCHUNK + chunk) * NS + t] = ssum;
    }
}

// ---------------- kernel 4: combine + GRU + MLP + LN + q (one batch per block) ----------------
__global__ __launch_bounds__(384) void update_kernel(const float* __restrict__ b_ih,
                                                     const float* __restrict__ b_hh,
                                                     const float* __restrict__ ln_mlp_g,
                                                     const float* __restrict__ ln_mlp_b,
                                                     const float* __restrict__ ln_slot_g,
                                                     const float* __restrict__ ln_slot_b,
                                                     const float* __restrict__ mlp_b1,
                                                     const float* __restrict__ mlp_b2,
                                                     float* __restrict__ out, int last) {
    __shared__ float S[NS];
    __shared__ float prev[NS * SD];
    __shared__ float upd[NS * SD];
    __shared__ float gi[NS * 192];
    __shared__ float gh[NS * 192];
    __shared__ float mln[NS * SD];
    __shared__ float m1[NS * 128];
    __shared__ float red[12][2];

    int b = blockIdx.x;
    int t = threadIdx.x;
    int s = t >> 6, h = t & 63;
    int wid = t >> 5, lane = t & 31;

    float u = 0.f;
#pragma unroll
    for (int c = 0; c < NCHUNK; c++)
        u += g_pU[(((unsigned)b * NCHUNK + c) * NS + s) * SD + h];
    if (h == 0) {
        float ss = 0.f;
#pragma unroll
        for (int c = 0; c < NCHUNK; c++) ss += g_pS[((unsigned)b * NCHUNK + c) * NS + s];
        S[s] = ss;
    }
    prev[t] = g_slots[b * 384 + t];
    __syncthreads();
    upd[t] = u / (S[s] + 1e-8f);
    __syncthreads();

#pragma unroll
    for (int g = 0; g < 6; g++) {
        int idx = t + g * 384;
        int half = idx / 1152;
        int r = idx - half * 1152;
        int s2 = r / 192, c = r - s2 * 192;
        const float* src = half ? prev : upd;
        const float* wT = half ? g_WhhT : g_WihT;
        float acc = half ? b_hh[c] : b_ih[c];
#pragma unroll
        for (int hh = 0; hh < SD; hh++) acc += src[s2 * SD + hh] * wT[hh * 192 + c];
        if (half) gh[s2 * 192 + c] = acc; else gi[s2 * 192 + c] = acc;
    }
    __syncthreads();

    float ir = gi[s * 192 + h], iz = gi[s * 192 + 64 + h], inn = gi[s * 192 + 128 + h];
    float hr = gh[s * 192 + h], hz = gh[s * 192 + 64 + h], hn = gh[s * 192 + 128 + h];
    float rg = 1.f / (1.f + expf(-(ir + hr)));
    float zg = 1.f / (1.f + expf(-(iz + hz)));
    float ng = tanhf(inn + rg * hn);
    float hv = (1.f - zg) * ng + zg * prev[t];

    {
        float sum = hv, sq = hv * hv;
        warp_red2(sum, sq);
        if (lane == 0) { red[wid][0] = sum; red[wid][1] = sq; }
    }
    __syncthreads();
    {
        float tsum = red[2 * s][0] + red[2 * s + 1][0];
        float tsq = red[2 * s][1] + red[2 * s + 1][1];
        float m = tsum * (1.f / 64.f);
        float var = tsq * (1.f / 64.f) - m * m;
        float rstd = rsqrtf(var + 1e-5f);
        mln[t] = (hv - m) * rstd * ln_mlp_g[h] + ln_mlp_b[h];
    }
    __syncthreads();

#pragma unroll
    for (int g = 0; g < 2; g++) {
        int idx = t + g * 384;
        int s2 = idx >> 7, c = idx & 127;
        float acc = mlp_b1[c];
#pragma unroll
        for (int hh = 0; hh < SD; hh++) acc += mln[s2 * SD + hh] * g_W1T[hh * 128 + c];
        m1[s2 * 128 + c] = fmaxf(acc, 0.f);
    }
    __syncthreads();

    float acc2 = mlp_b2[h];
#pragma unroll
    for (int c = 0; c < 128; c++) acc2 += m1[s * 128 + c] * g_W2T[c * SD + h];
    float snew = hv + acc2;
    g_slots[b * 384 + t] = snew;
    if (last) {
        out[b * 384 + t] = snew;
    } else {
        __syncthreads();
        {
            float sum = snew, sq = snew * snew;
            warp_red2(sum, sq);
            if (lane == 0) { red[wid][0] = sum; red[wid][1] = sq; }
        }
        __syncthreads();
        {
            float tsum = red[2 * s][0] + red[2 * s + 1][0];
            float tsq = red[2 * s][1] + red[2 * s + 1][1];
            float m = tsum * (1.f / 64.f);
            float var = tsq * (1.f / 64.f) - m * m;
            float rstd = rsqrtf(var + 1e-5f);
            mln[t] = (snew - m) * rstd * ln_slot_g[h] + ln_slot_b[h];
        }
        __syncthreads();
        float qv = 0.f;
#pragma unroll
        for (int hh = 0; hh < SD; hh++) qv += mln[s * SD + hh] * g_WqT[hh * SD + h];
        g_q[b * 384 + t] = qv;
    }
}

// ---------------- launch ----------------
extern "C" void kernel_launch(void* const* d_in, const int* in_sizes, int n_in,
                              void* d_out, int out_size) {
    const float* features   = (const float*)d_in[0];
    const float* slot_noise = (const float*)d_in[1];
    const float* slot_mu    = (const float*)d_in[2];
    const float* slot_sigma = (const float*)d_in[3];
    const float* ln_feat_g  = (const float*)d_in[4];
    const float* ln_feat_b  = (const float*)d_in[5];
    const float* ln_slot_g  = (const float*)d_in[6];
    const float* ln_slot_b  = (const float*)d_in[7];
    const float* ln_mlp_g   = (const float*)d_in[8];
    const float* ln_mlp_b   = (const float*)d_in[9];
    const float* Wk         = (const float*)d_in[10];
    const float* Wv         = (const float*)d_in[11];
    const float* Wq         = (const float*)d_in[12];
    const float* W_ih       = (const float*)d_in[13];
    const float* W_hh       = (const float*)d_in[14];
    const float* b_ih       = (const float*)d_in[15];
    const float* b_hh       = (const float*)d_in[16];
    const float* mlp_W1     = (const float*)d_in[17];
    const float* mlp_b1     = (const float*)d_in[18];
    const float* mlp_W2     = (const float*)d_in[19];
    const float* mlp_b2     = (const float*)d_in[20];
    float* out = (float*)d_out;

    cudaFuncSetAttribute(proj_mma_kernel, cudaFuncAttributeMaxDynamicSharedMemorySize, PROJ_SMEM);

    transpose_kernel<<<64, 256>>>(Wk, Wv, Wq, W_ih, W_hh, mlp_W1, mlp_W2, ln_feat_g, ln_feat_b);
    init_kernel<<<BB, 384>>>(slot_noise, slot_mu, slot_sigma, ln_slot_g, ln_slot_b);
    proj_mma_kernel<<<2048, 512, PROJ_SMEM>>>(features);
    for (int it = 0; it < 3; it++) {
        attn_kernel<<<BB * NCHUNK, 192>>>();
        update_kernel<<<BB, 384>>>(b_ih, b_hh, ln_mlp_g, ln_mlp_b, ln_slot_g, ln_slot_b,
                                   mlp_b1, mlp_b2, out, it == 2);
    }
}

// round 6
// speedup vs baseline: 2.2889x; 1.2128x over previous
#include <cuda_runtime.h>
#include <cuda_bf16.h>
#include <math.h>
#include <stdint.h>

#define BB 64
#define NN 4096
#define FEAT 256
#define NS 6
#define SD 64
#define NCHUNK 8

// ---------------- scratch (device globals: no allocs allowed) ----------------
__device__ float g_kT[BB * SD * NN];         // 64 MB  [b][d][n]
__device__ float g_v[BB * NN * SD];          // 64 MB  [b*n][h]
__device__ __nv_bfloat16 g_Whi[128 * 256];   // (W*g) hi  [n][k]
__device__ __nv_bfloat16 g_Wlo[128 * 256];   // (W*g) lo  [n][k]
__device__ float g_c1[128];                  // W @ ln_feat_b
__device__ float g_c2[128];                  // W @ ln_feat_g
__device__ float g_WqT[SD * SD];
__device__ float g_WihT[SD * 192];
__device__ float g_WhhT[SD * 192];
__device__ float g_W1T[SD * 128];
__device__ float g_W2T[128 * SD];
__device__ float g_slots[BB * NS * SD];
__device__ float g_q[BB * NS * SD];
__device__ float g_pU[BB * NCHUNK * NS * SD];
__device__ float g_pS[BB * NCHUNK * NS];

__device__ __forceinline__ void warp_red2(float& a, float& b) {
#pragma unroll
    for (int o = 16; o; o >>= 1) {
        a += __shfl_xor_sync(0xffffffffu, a, o);
        b += __shfl_xor_sync(0xffffffffu, b, o);
    }
}

__device__ __forceinline__ uint32_t smem_u32(const void* p) {
    uint32_t a;
    asm("{ .reg .u64 t; cvta.to.shared.u64 t, %1; cvt.u32.u64 %0, t; }" : "=r"(a) : "l"(p));
    return a;
}

__device__ __forceinline__ void ldsm_x4(uint32_t* r, uint32_t addr) {
    asm volatile("ldmatrix.sync.aligned.m8n8.x4.shared.b16 {%0,%1,%2,%3}, [%4];"
                 : "=r"(r[0]), "=r"(r[1]), "=r"(r[2]), "=r"(r[3]) : "r"(addr));
}

__device__ __forceinline__ void mma_bf16(float* c, const uint32_t* a, uint32_t b0, uint32_t b1) {
    asm volatile(
        "mma.sync.aligned.m16n8k16.row.col.f32.bf16.bf16.f32 "
        "{%0,%1,%2,%3}, {%4,%5,%6,%7}, {%8,%9}, {%0,%1,%2,%3};"
        : "+f"(c[0]), "+f"(c[1]), "+f"(c[2]), "+f"(c[3])
        : "r"(a[0]), "r"(a[1]), "r"(a[2]), "r"(a[3]), "r"(b0), "r"(b1));
}

// ---------------- kernel 0: stage weights ----------------
__global__ void transpose_kernel(const float* __restrict__ Wk, const float* __restrict__ Wv,
                                 const float* __restrict__ Wq, const float* __restrict__ Wih,
                                 const float* __restrict__ Whh, const float* __restrict__ W1,
                                 const float* __restrict__ W2, const float* __restrict__ lfg,
                                 const float* __restrict__ lfb) {
    int tid = blockIdx.x * 256 + threadIdx.x;
    const int stride = 64 * 256;
    for (int idx = tid; idx < 128 * 256; idx += stride) {
        int n = idx >> 8, k = idx & 255;
        float w = ((n < 64) ? Wk[n * FEAT + k] : Wv[(n - 64) * FEAT + k]) * lfg[k];
        __nv_bfloat16 hi = __float2bfloat16(w);
        __nv_bfloat16 lo = __float2bfloat16(w - __bfloat162float(hi));
        g_Whi[idx] = hi;
        g_Wlo[idx] = lo;
    }
    if (blockIdx.x == 0) {
        int t = threadIdx.x;
        int n = t & 127;
        const float* Wr = (n < 64) ? (Wk + n * FEAT) : (Wv + (n - 64) * FEAT);
        const float* vec = (t < 128) ? lfb : lfg;
        float acc = 0.f;
        for (int k = 0; k < 256; k++) acc += Wr[k] * vec[k];
        if (t < 128) g_c1[n] = acc; else g_c2[n] = acc;
    }
    for (int idx = tid; idx < SD * SD; idx += stride) {
        int h = idx >> 6, g = idx & 63;
        g_WqT[idx] = Wq[g * SD + h];
    }
    for (int idx = tid; idx < SD * 192; idx += stride) {
        int h = idx / 192, c = idx % 192;
        g_WihT[idx] = Wih[c * SD + h];
        g_WhhT[idx] = Whh[c * SD + h];
    }
    for (int idx = tid; idx < SD * 128; idx += stride) {
        int h = idx >> 7, c = idx & 127;
        g_W1T[idx] = W1[c * SD + h];
    }
    for (int idx = tid; idx < 128 * SD; idx += stride) {
        int c = idx >> 6, h = idx & 63;
        g_W2T[idx] = W2[h * 128 + c];
    }
}

// ---------------- kernel 1: slots init + q0 ----------------
__global__ __launch_bounds__(384) void init_kernel(const float* __restrict__ noise,
                                                   const float* __restrict__ mu,
                                                   const float* __restrict__ sigma,
                                                   const float* __restrict__ lng,
                                                   const float* __restrict__ lnb) {
    __shared__ float sln[NS * SD];
    __shared__ float red[12][2];
    int b = blockIdx.x;
    int t = threadIdx.x;
    int s = t >> 6, h = t & 63;
    int wid = t >> 5, lane = t & 31;

    float sv = mu[h] + sigma[h] * noise[b * 384 + t];
    g_slots[b * 384 + t] = sv;

    float sum = sv, sq = sv * sv;
    warp_red2(sum, sq);
    if (lane == 0) { red[wid][0] = sum; red[wid][1] = sq; }
    __syncthreads();
    float tsum = red[2 * s][0] + red[2 * s + 1][0];
    float tsq = red[2 * s][1] + red[2 * s + 1][1];
    float m = tsum * (1.f / 64.f);
    float var = tsq * (1.f / 64.f) - m * m;
    float rstd = rsqrtf(var + 1e-5f);
    sln[t] = (sv - m) * rstd * lng[h] + lnb[h];
    __syncthreads();
    float qv = 0.f;
#pragma unroll
    for (int hh = 0; hh < SD; hh++) qv += sln[s * SD + hh] * g_WqT[hh * SD + h];
    g_q[b * 384 + t] = qv;
}

// ---------------- kernel 2: K/V projection, K-chunked for 2 CTAs/SM ----------------
#define PST 144                     // bytes per row in each chunk buffer (64 bf16 + 16 pad)
#define ACH (128 * PST)             // 18432 per buffer
#define OFF_MR  0                   // [128][2] floats
#define OFF_C1  1024
#define OFF_C2  1536
#define OFF_AHI 2048
#define OFF_ALO (OFF_AHI + ACH)
#define OFF_BHI (OFF_ALO + ACH)
#define OFF_BLO (OFF_BHI + ACH)
#define PROJ_SMEM (OFF_BLO + ACH)   // 75776

__global__ __launch_bounds__(512, 2) void proj_mma_kernel(const float* __restrict__ feat) {
    extern __shared__ char smem[];
    uint32_t sbase = smem_u32(smem);
    int t = threadIdx.x, wid = t >> 5, lane = t & 31;
    int wm = wid >> 2, wn = wid & 3;   // warp grid 4(M) x 4(N); warp tile 32x32
    float* mr = (float*)(smem + OFF_MR);
    float* c1s = (float*)(smem + OFF_C1);
    float* c2s = (float*)(smem + OFF_C2);

    if (t < 128) { c1s[t] = g_c1[t]; c2s[t] = g_c2[t]; }

    const float* tileA = feat + (size_t)blockIdx.x * 128 * FEAT;
    int row = t >> 2, seg = t & 3;
    const float* arow_p = tileA + row * FEAT + seg * 16;
    float runs = 0.f, runq = 0.f;

    float acc[2][4][4];
#pragma unroll
    for (int a = 0; a < 2; a++)
#pragma unroll
        for (int b = 0; b < 4; b++)
#pragma unroll
            for (int c = 0; c < 4; c++) acc[a][b][c] = 0.f;

    int arow = wm * 32 + (lane & 15);
    int akh = (lane >> 4) * 8;
    int bg = lane >> 3;
    int brow = wn * 32 + ((bg >> 1) * 8) + (lane & 7);
    int bkh = (bg & 1) * 8;

    for (int c = 0; c < 4; c++) {
        __syncthreads();    // prior chunk consumers done
        // A chunk: load 16 raw floats, accumulate stats, split hi/lo
#pragma unroll
        for (int j = 0; j < 4; j++) {
            float4 x = *(const float4*)(arow_p + c * 64 + j * 4);
            runs += x.x + x.y + x.z + x.w;
            runq += x.x * x.x + x.y * x.y + x.z * x.z + x.w * x.w;
            __nv_bfloat16 h0 = __float2bfloat16(x.x), h1 = __float2bfloat16(x.y);
            __nv_bfloat16 h2 = __float2bfloat16(x.z), h3 = __float2bfloat16(x.w);
            __nv_bfloat16 l0 = __float2bfloat16(x.x - __bfloat162float(h0));
            __nv_bfloat16 l1 = __float2bfloat16(x.y - __bfloat162float(h1));
            __nv_bfloat16 l2 = __float2bfloat16(x.z - __bfloat162float(h2));
            __nv_bfloat16 l3 = __float2bfloat16(x.w - __bfloat162float(h3));
            uint2 hw, lw;
            hw.x = (uint32_t)__bfloat16_as_ushort(h0) | ((uint32_t)__bfloat16_as_ushort(h1) << 16);
            hw.y = (uint32_t)__bfloat16_as_ushort(h2) | ((uint32_t)__bfloat16_as_ushort(h3) << 16);
            lw.x = (uint32_t)__bfloat16_as_ushort(l0) | ((uint32_t)__bfloat16_as_ushort(l1) << 16);
            lw.y = (uint32_t)__bfloat16_as_ushort(l2) | ((uint32_t)__bfloat16_as_ushort(l3) << 16);
            unsigned off = (unsigned)row * PST + (unsigned)(seg * 16 + j * 4) * 2u;
            *(uint2*)(smem + OFF_AHI + off) = hw;
            *(uint2*)(smem + OFF_ALO + off) = lw;
        }
        // B chunk
#pragma unroll
        for (int rep = 0; rep < 2; rep++) {
            int i = t + rep * 512;
            int n = i >> 3, j = i & 7;
            unsigned so = (unsigned)n * PST + (unsigned)j * 16u;
            *(uint4*)(smem + OFF_BHI + so) = *(const uint4*)(g_Whi + n * 256 + c * 64 + j * 8);
            *(uint4*)(smem + OFF_BLO + so) = *(const uint4*)(g_Wlo + n * 256 + c * 64 + j * 8);
        }
        __syncthreads();

#pragma unroll
        for (int ks = 0; ks < 4; ks++) {
            int kb = ks * 16;
            uint32_t ah[2][4], al[2][4], bh[2][4], bl[2][4];
#pragma unroll
            for (int mi = 0; mi < 2; mi++) {
                uint32_t ao = sbase + (uint32_t)((arow + mi * 16) * PST + (kb + akh) * 2);
                ldsm_x4(ah[mi], ao + OFF_AHI);
                ldsm_x4(al[mi], ao + OFF_ALO);
            }
#pragma unroll
            for (int p = 0; p < 2; p++) {
                uint32_t bo = sbase + (uint32_t)((brow + p * 16) * PST + (kb + bkh) * 2);
                ldsm_x4(bh[p], bo + OFF_BHI);
                ldsm_x4(bl[p], bo + OFF_BLO);
            }
#pragma unroll
            for (int mi = 0; mi < 2; mi++)
#pragma unroll
                for (int ni = 0; ni < 4; ni++) {
                    int p = ni >> 1, rp = (ni & 1) * 2;
                    mma_bf16(acc[mi][ni], ah[mi], bh[p][rp], bh[p][rp + 1]);
                    mma_bf16(acc[mi][ni], ah[mi], bl[p][rp], bl[p][rp + 1]);
                    mma_bf16(acc[mi][ni], al[mi], bh[p][rp], bh[p][rp + 1]);
                }
        }
    }

    // finalize LN stats (4 threads per row)
    runs += __shfl_xor_sync(0xffffffffu, runs, 1);
    runq += __shfl_xor_sync(0xffffffffu, runq, 1);
    runs += __shfl_xor_sync(0xffffffffu, runs, 2);
    runq += __shfl_xor_sync(0xffffffffu, runq, 2);
    if (seg == 0) {
        float m = runs * (1.f / 256.f);
        float var = runq * (1.f / 256.f) - m * m;
        mr[row * 2] = m;
        mr[row * 2 + 1] = rsqrtf(var + 1e-5f);
    }
    __syncthreads();

    // epilogue: out = r*p + c1[n] - m*r*c2[n]; n<64 -> g_kT[b][d][n], else g_v
    int qr = lane >> 2, qc = lane & 3;
#pragma unroll
    for (int mi = 0; mi < 2; mi++) {
        int lrow = wm * 32 + mi * 16 + qr;
        float m0 = mr[lrow * 2], r0 = mr[lrow * 2 + 1];
        float m1 = mr[(lrow + 8) * 2], r1 = mr[(lrow + 8) * 2 + 1];
        unsigned g0 = blockIdx.x * 128u + lrow;
        unsigned g1 = g0 + 8;
        unsigned bidx = g0 >> 12;
        unsigned np0 = g0 & 4095u, np1 = g1 & 4095u;
#pragma unroll
        for (int ni = 0; ni < 4; ni++) {
            int n = wn * 32 + ni * 8 + 2 * qc;
            float C1a = c1s[n], C2a = c2s[n], C1b = c1s[n + 1], C2b = c2s[n + 1];
            float v00 = fmaf(r0, acc[mi][ni][0], fmaf(-m0 * r0, C2a, C1a));
            float v01 = fmaf(r0, acc[mi][ni][1], fmaf(-m0 * r0, C2b, C1b));
            float v10 = fmaf(r1, acc[mi][ni][2], fmaf(-m1 * r1, C2a, C1a));
            float v11 = fmaf(r1, acc[mi][ni][3], fmaf(-m1 * r1, C2b, C1b));
            if (n < 64) {
                float* kb0 = g_kT + (size_t)bidx * (SD * NN) + (size_t)n * NN;
                kb0[np0] = v00;
                kb0[np1] = v10;
                kb0[NN + np0] = v01;
                kb0[NN + np1] = v11;
            } else {
                int hh = n - 64;
                *(float2*)(g_v + (size_t)g0 * SD + hh) = make_float2(v00, v01);
                *(float2*)(g_v + (size_t)g1 * SD + hh) = make_float2(v10, v11);
            }
        }
    }
}

// ---------------- kernel 3: attention pass, gmem-direct k/v (256 thr, 512 n per block) ----------------
__global__ __launch_bounds__(256) void attn_kernel() {
    __shared__ float qs[384];
    __shared__ float lgp[2 * NS * 512];   // partial logits; reused as pUw[8][NS][64]
    __shared__ float att[NS * 512];
    __shared__ float srw[4 * NS];

    int t = threadIdx.x;
    int b = blockIdx.x >> 3;
    int chunk = blockIdx.x & 7;
    int w = t >> 5, lane = t & 31;
    int dh = t >> 7;            // warps 0-3: d 0..31, warps 4-7: d 32..63
    int nq = t & 127;           // float4 group of n

    const float* kTb = g_kT + (size_t)b * (SD * NN) + chunk * 512;
    const float* vB = g_v + ((size_t)b * NN + chunk * 512) * SD;

    for (int i = t; i < 384; i += 256) qs[i] = g_q[b * 384 + i];
    __syncthreads();

    // phase 1: partial logits over the thread's d-half, 4 n per thread
    float4 lg[NS];
#pragma unroll
    for (int s = 0; s < NS; s++) lg[s] = make_float4(0.f, 0.f, 0.f, 0.f);
#pragma unroll 4
    for (int i = 0; i < 32; i++) {
        int d = dh * 32 + i;
        float4 k4 = *(const float4*)(kTb + (size_t)d * NN + nq * 4);
#pragma unroll
        for (int s = 0; s < NS; s++) {
            float qv = qs[s * 64 + d];
            lg[s].x += qv * k4.x;
            lg[s].y += qv * k4.y;
            lg[s].z += qv * k4.z;
            lg[s].w += qv * k4.w;
        }
    }
#pragma unroll
    for (int s = 0; s < NS; s++)
        *(float4*)(lgp + (dh * NS + s) * 512 + nq * 4) = lg[s];
    __syncthreads();

    // phase 2: combine halves + softmax over slots (threads 0-127, 4 n each)
    float sred[NS] = {0.f, 0.f, 0.f, 0.f, 0.f, 0.f};
    if (t < 128) {
        float lv[NS][4];
#pragma unroll
        for (int s = 0; s < NS; s++) {
            float4 a = *(const float4*)(lgp + s * 512 + t * 4);
            float4 bq = *(const float4*)(lgp + (NS + s) * 512 + t * 4);
            lv[s][0] = (a.x + bq.x) * 0.125f;
            lv[s][1] = (a.y + bq.y) * 0.125f;
            lv[s][2] = (a.z + bq.z) * 0.125f;
            lv[s][3] = (a.w + bq.w) * 0.125f;
        }
        float av[NS][4];
#pragma unroll
        for (int e = 0; e < 4; e++) {
            float mx = -1e30f;
#pragma unroll
            for (int s = 0; s < NS; s++) mx = fmaxf(mx, lv[s][e]);
            float den = 0.f;
#pragma unroll
            for (int s = 0; s < NS; s++) { av[s][e] = expf(lv[s][e] - mx); den += av[s][e]; }
            float inv = 1.f / den;
#pragma unroll
            for (int s = 0; s < NS; s++) { av[s][e] *= inv; sred[s] += av[s][e]; }
        }
#pragma unroll
        for (int s = 0; s < NS; s++)
            *(float4*)(att + s * 512 + t * 4) = make_float4(av[s][0], av[s][1], av[s][2], av[s][3]);
    }
    __syncthreads();

    // phase 3: updates; warp owns 64 n, lane owns h-quad, 2 n per iteration
    float accU[NS][4];
#pragma unroll
    for (int s = 0; s < NS; s++)
#pragma unroll
        for (int e = 0; e < 4; e++) accU[s][e] = 0.f;
    int nsub = lane >> 4;
    int h4 = (lane & 15) * 4;
#pragma unroll 4
    for (int i = 0; i < 32; i++) {
        int n = w * 64 + 2 * i + nsub;
        float4 v4 = *(const float4*)(vB + (size_t)n * SD + h4);
#pragma unroll
        for (int s = 0; s < NS; s++) {
            float a = att[s * 512 + n];
            accU[s][0] += a * v4.x;
            accU[s][1] += a * v4.y;
            accU[s][2] += a * v4.z;
            accU[s][3] += a * v4.w;
        }
    }
    // fold the two n-halves of the warp
#pragma unroll
    for (int s = 0; s < NS; s++)
#pragma unroll
        for (int e = 0; e < 4; e++)
            accU[s][e] += __shfl_xor_sync(0xffffffffu, accU[s][e], 16);
    float* pUw = lgp;   // lgp is dead now
    if (lane < 16) {
#pragma unroll
        for (int s = 0; s < NS; s++)
            *(float4*)(pUw + (w * NS + s) * 64 + h4) =
                make_float4(accU[s][0], accU[s][1], accU[s][2], accU[s][3]);
    }
    // sred reduction (warps 0-3 hold it)
    if (t < 128) {
#pragma unroll
        for (int s = 0; s < NS; s++) {
            float v = sred[s];
#pragma unroll
            for (int o = 16; o; o >>= 1) v += __shfl_xor_sync(0xffffffffu, v, o);
            if (lane == 0) srw[w * NS + s] = v;
        }
    }
    __syncthreads();

    for (int idx = t; idx < NS * SD; idx += 256) {
        int s = idx >> 6, h = idx & 63;
        float sum = 0.f;
#pragma unroll
        for (int w2 = 0; w2 < 8; w2++) sum += pUw[(w2 * NS + s) * 64 + h];
        g_pU[(((size_t)b * NCHUNK + chunk) * NS + s) * SD + h] = sum;
    }
    if (t < NS) {
        float ss = srw[t] + srw[NS + t] + srw[2 * NS + t] + srw[3 * NS + t];
        g_pS[((unsigned)b * NCHUNK + chunk) * NS + t] = ss;
    }
}

// ---------------- kernel 4: combine + GRU + MLP + LN + q (one batch per block) ----------------
__global__ __launch_bounds__(384) void update_kernel(const float* __restrict__ b_ih,
                                                     const float* __restrict__ b_hh,
                                                     const float* __restrict__ ln_mlp_g,
                                                     const float* __restrict__ ln_mlp_b,
                                                     const float* __restrict__ ln_slot_g,
                                                     const float* __restrict__ ln_slot_b,
                                                     const float* __restrict__ mlp_b1,
                                                     const float* __restrict__ mlp_b2,
                                                     float* __restrict__ out, int last) {
    __shared__ float S[NS];
    __shared__ float prev[NS * SD];
    __shared__ float upd[NS * SD];
    __shared__ float gi[NS * 192];
    __shared__ float gh[NS * 192];
    __shared__ float mln[NS * SD];
    __shared__ float m1[NS * 128];
    __shared__ float red[12][2];

    int b = blockIdx.x;
    int t = threadIdx.x;
    int s = t >> 6, h = t & 63;
    int wid = t >> 5, lane = t & 31;

    float u = 0.f;
#pragma unroll
    for (int c = 0; c < NCHUNK; c++)
        u += g_pU[(((unsigned)b * NCHUNK + c) * NS + s) * SD + h];
    if (h == 0) {
        float ss = 0.f;
#pragma unroll
        for (int c = 0; c < NCHUNK; c++) ss += g_pS[((unsigned)b * NCHUNK + c) * NS + s];
        S[s] = ss;
    }
    prev[t] = g_slots[b * 384 + t];
    __syncthreads();
    upd[t] = u / (S[s] + 1e-8f);
    __syncthreads();

#pragma unroll
    for (int g = 0; g < 6; g++) {
        int idx = t + g * 384;
        int half = idx / 1152;
        int r = idx - half * 1152;
        int s2 = r / 192, c = r - s2 * 192;
        const float* src = half ? prev : upd;
        const float* wT = half ? g_WhhT : g_WihT;
        float acc = half ? b_hh[c] : b_ih[c];
#pragma unroll
        for (int hh = 0; hh < SD; hh++) acc += src[s2 * SD + hh] * wT[hh * 192 + c];
        if (half) gh[s2 * 192 + c] = acc; else gi[s2 * 192 + c] = acc;
    }
    __syncthreads();

    float ir = gi[s * 192 + h], iz = gi[s * 192 + 64 + h], inn = gi[s * 192 + 128 + h];
    float hr = gh[s * 192 + h], hz = gh[s * 192 + 64 + h], hn = gh[s * 192 + 128 + h];
    float rg = 1.f / (1.f + expf(-(ir + hr)));
    float zg = 1.f / (1.f + expf(-(iz + hz)));
    float ng = tanhf(inn + rg * hn);
    float hv = (1.f - zg) * ng + zg * prev[t];

    {
        float sum = hv, sq = hv * hv;
        warp_red2(sum, sq);
        if (lane == 0) { red[wid][0] = sum; red[wid][1] = sq; }
    }
    __syncthreads();
    {
        float tsum = red[2 * s][0] + red[2 * s + 1][0];
        float tsq = red[2 * s][1] + red[2 * s + 1][1];
        float m = tsum * (1.f / 64.f);
        float var = tsq * (1.f / 64.f) - m * m;
        float rstd = rsqrtf(var + 1e-5f);
        mln[t] = (hv - m) * rstd * ln_mlp_g[h] + ln_mlp_b[h];
    }
    __syncthreads();

#pragma unroll
    for (int g = 0; g < 2; g++) {
        int idx = t + g * 384;
        int s2 = idx >> 7, c = idx & 127;
        float acc = mlp_b1[c];
#pragma unroll
        for (int hh = 0; hh < SD; hh++) acc += mln[s2 * SD + hh] * g_W1T[hh * 128 + c];
        m1[s2 * 128 + c] = fmaxf(acc, 0.f);
    }
    __syncthreads();

    float acc2 = mlp_b2[h];
#pragma unroll
    for (int c = 0; c < 128; c++) acc2 += m1[s * 128 + c] * g_W2T[c * SD + h];
    float snew = hv + acc2;
    g_slots[b * 384 + t] = snew;
    if (last) {
        out[b * 384 + t] = snew;
    } else {
        __syncthreads();
        {
            float sum = snew, sq = snew * snew;
            warp_red2(sum, sq);
            if (lane == 0) { red[wid][0] = sum; red[wid][1] = sq; }
        }
        __syncthreads();
        {
            float tsum = red[2 * s][0] + red[2 * s + 1][0];
            float tsq = red[2 * s][1] + red[2 * s + 1][1];
            float m = tsum * (1.f / 64.f);
            float var = tsq * (1.f / 64.f) - m * m;
            float rstd = rsqrtf(var + 1e-5f);
            mln[t] = (snew - m) * rstd * ln_slot_g[h] + ln_slot_b[h];
        }
        __syncthreads();
        float qv = 0.f;
#pragma unroll
        for (int hh = 0; hh < SD; hh++) qv += mln[s * SD + hh] * g_WqT[hh * SD + h];
        g_q[b * 384 + t] = qv;
    }
}

// ---------------- launch ----------------
extern "C" void kernel_launch(void* const* d_in, const int* in_sizes, int n_in,
                              void* d_out, int out_size) {
    const float* features   = (const float*)d_in[0];
    const float* slot_noise = (const float*)d_in[1];
    const float* slot_mu    = (const float*)d_in[2];
    const float* slot_sigma = (const float*)d_in[3];
    const float* ln_feat_g  = (const float*)d_in[4];
    const float* ln_feat_b  = (const float*)d_in[5];
    const float* ln_slot_g  = (const float*)d_in[6];
    const float* ln_slot_b  = (const float*)d_in[7];
    const float* ln_mlp_g   = (const float*)d_in[8];
    const float* ln_mlp_b   = (const float*)d_in[9];
    const float* Wk         = (const float*)d_in[10];
    const float* Wv         = (const float*)d_in[11];
    const float* Wq         = (const float*)d_in[12];
    const float* W_ih       = (const float*)d_in[13];
    const float* W_hh       = (const float*)d_in[14];
    const float* b_ih       = (const float*)d_in[15];
    const float* b_hh       = (const float*)d_in[16];
    const float* mlp_W1     = (const float*)d_in[17];
    const float* mlp_b1     = (const float*)d_in[18];
    const float* mlp_W2     = (const float*)d_in[19];
    const float* mlp_b2     = (const float*)d_in[20];
    float* out = (float*)d_out;

    cudaFuncSetAttribute(proj_mma_kernel, cudaFuncAttributeMaxDynamicSharedMemorySize, PROJ_SMEM);

    transpose_kernel<<<64, 256>>>(Wk, Wv, Wq, W_ih, W_hh, mlp_W1, mlp_W2, ln_feat_g, ln_feat_b);
    init_kernel<<<BB, 384>>>(slot_noise, slot_mu, slot_sigma, ln_slot_g, ln_slot_b);
    proj_mma_kernel<<<2048, 512, PROJ_SMEM>>>(features);
    for (int it = 0; it < 3; it++) {
        attn_kernel<<<BB * NCHUNK, 256>>>();
        update_kernel<<<BB, 384>>>(b_ih, b_hh, ln_mlp_g, ln_mlp_b, ln_slot_g, ln_slot_b,
                                   mlp_b1, mlp_b2, out, it == 2);
    }
}

// round 8
// speedup vs baseline: 2.3034x; 1.0064x over previous
#include <cuda_runtime.h>
#include <cuda_bf16.h>
#include <math.h>
#include <stdint.h>

#define BB 64
#define NN 4096
#define FEAT 256
#define NS 6
#define SD 64
#define NCHUNK 8

// ---------------- scratch (device globals: no allocs allowed) ----------------
__device__ float g_kT[BB * SD * NN];         // 64 MB  [b][d][n]
__device__ float g_v[BB * NN * SD];          // 64 MB  [b*n][h]
__device__ __nv_bfloat16 g_Whi[128 * 256];   // (W*g) hi  [n][k]
__device__ __nv_bfloat16 g_Wlo[128 * 256];   // (W*g) lo  [n][k]
__device__ float g_c1[128];                  // W @ ln_feat_b
__device__ float g_c2[128];                  // W @ ln_feat_g
__device__ float g_WqT[SD * SD];
__device__ float g_WihT[SD * 192];
__device__ float g_WhhT[SD * 192];
__device__ float g_W1T[SD * 128];
__device__ float g_W2T[128 * SD];
__device__ float g_slots[BB * NS * SD];
__device__ float g_q[BB * NS * SD];
__device__ float g_pU[BB * NCHUNK * NS * SD];
__device__ float g_pS[BB * NCHUNK * NS];

__device__ __forceinline__ void warp_red2(float& a, float& b) {
#pragma unroll
    for (int o = 16; o; o >>= 1) {
        a += __shfl_xor_sync(0xffffffffu, a, o);
        b += __shfl_xor_sync(0xffffffffu, b, o);
    }
}

__device__ __forceinline__ uint32_t smem_u32(const void* p) {
    uint32_t a;
    asm("{ .reg .u64 t; cvta.to.shared.u64 t, %1; cvt.u32.u64 %0, t; }" : "=r"(a) : "l"(p));
    return a;
}

__device__ __forceinline__ void ldsm_x4(uint32_t* r, uint32_t addr) {
    asm volatile("ldmatrix.sync.aligned.m8n8.x4.shared.b16 {%0,%1,%2,%3}, [%4];"
                 : "=r"(r[0]), "=r"(r[1]), "=r"(r[2]), "=r"(r[3]) : "r"(addr));
}

__device__ __forceinline__ void mma_bf16(float* c, const uint32_t* a, uint32_t b0, uint32_t b1) {
    asm volatile(
        "mma.sync.aligned.m16n8k16.row.col.f32.bf16.bf16.f32 "
        "{%0,%1,%2,%3}, {%4,%5,%6,%7}, {%8,%9}, {%0,%1,%2,%3};"
        : "+f"(c[0]), "+f"(c[1]), "+f"(c[2]), "+f"(c[3])
        : "r"(a[0]), "r"(a[1]), "r"(a[2]), "r"(a[3]), "r"(b0), "r"(b1));
}

__device__ __forceinline__ void cp_async16(uint32_t saddr, const void* g) {
    asm volatile("cp.async.cg.shared.global [%0], [%1], 16;" :: "r"(saddr), "l"(g));
}
__device__ __forceinline__ void cp_commit() { asm volatile("cp.async.commit_group;"); }
__device__ __forceinline__ void cp_wait0() { asm volatile("cp.async.wait_group 0;"); }

// ---------------- kernel 0: stage weights ----------------
__global__ void transpose_kernel(const float* __restrict__ Wk, const float* __restrict__ Wv,
                                 const float* __restrict__ Wq, const float* __restrict__ Wih,
                                 const float* __restrict__ Whh, const float* __restrict__ W1,
                                 const float* __restrict__ W2, const float* __restrict__ lfg,
                                 const float* __restrict__ lfb) {
    int tid = blockIdx.x * 256 + threadIdx.x;
    const int stride = 64 * 256;
    for (int idx = tid; idx < 128 * 256; idx += stride) {
        int n = idx >> 8, k = idx & 255;
        float w = ((n < 64) ? Wk[n * FEAT + k] : Wv[(n - 64) * FEAT + k]) * lfg[k];
        __nv_bfloat16 hi = __float2bfloat16(w);
        __nv_bfloat16 lo = __float2bfloat16(w - __bfloat162float(hi));
        g_Whi[idx] = hi;
        g_Wlo[idx] = lo;
    }
    if (blockIdx.x == 0) {
        int t = threadIdx.x;
        int n = t & 127;
        const float* Wr = (n < 64) ? (Wk + n * FEAT) : (Wv + (n - 64) * FEAT);
        const float* vec = (t < 128) ? lfb : lfg;
        float acc = 0.f;
        for (int k = 0; k < 256; k++) acc += Wr[k] * vec[k];
        if (t < 128) g_c1[n] = acc; else g_c2[n] = acc;
    }
    for (int idx = tid; idx < SD * SD; idx += stride) {
        int h = idx >> 6, g = idx & 63;
        g_WqT[idx] = Wq[g * SD + h];
    }
    for (int idx = tid; idx < SD * 192; idx += stride) {
        int h = idx / 192, c = idx % 192;
        g_WihT[idx] = Wih[c * SD + h];
        g_WhhT[idx] = Whh[c * SD + h];
    }
    for (int idx = tid; idx < SD * 128; idx += stride) {
        int h = idx >> 7, c = idx & 127;
        g_W1T[idx] = W1[c * SD + h];
    }
    for (int idx = tid; idx < 128 * SD; idx += stride) {
        int c = idx >> 6, h = idx & 63;
        g_W2T[idx] = W2[h * 128 + c];
    }
}

// ---------------- kernel 1: slots init + q0 ----------------
__global__ __launch_bounds__(384) void init_kernel(const float* __restrict__ noise,
                                                   const float* __restrict__ mu,
                                                   const float* __restrict__ sigma,
                                                   const float* __restrict__ lng,
                                                   const float* __restrict__ lnb) {
    __shared__ float sln[NS * SD];
    __shared__ float red[12][2];
    int b = blockIdx.x;
    int t = threadIdx.x;
    int s = t >> 6, h = t & 63;
    int wid = t >> 5, lane = t & 31;

    float sv = mu[h] + sigma[h] * noise[b * 384 + t];
    g_slots[b * 384 + t] = sv;

    float sum = sv, sq = sv * sv;
    warp_red2(sum, sq);
    if (lane == 0) { red[wid][0] = sum; red[wid][1] = sq; }
    __syncthreads();
    float tsum = red[2 * s][0] + red[2 * s + 1][0];
    float tsq = red[2 * s][1] + red[2 * s + 1][1];
    float m = tsum * (1.f / 64.f);
    float var = tsq * (1.f / 64.f) - m * m;
    float rstd = rsqrtf(var + 1e-5f);
    sln[t] = (sv - m) * rstd * lng[h] + lnb[h];
    __syncthreads();
    float qv = 0.f;
#pragma unroll
    for (int hh = 0; hh < SD; hh++) qv += sln[s * SD + hh] * g_WqT[hh * SD + h];
    g_q[b * 384 + t] = qv;
}

// ---------------- kernel 2: K/V projection, cp.async pipelined + coalesced epilogue ----------------
#define PST 144                     // bytes per row in A/B chunk buffers
#define ACH (128 * PST)             // 18432
#define STG 272                     // raw fp32 stage row stride bytes (64 floats + 16B pad)
#define OFF_MR   0                  // [128][2] floats
#define OFF_C1   1024
#define OFF_C2   1536
#define OFF_STAGE 2048              // 128*272 = 34816 -> ends 36864
#define OFF_AHI  36864
#define OFF_ALO  (OFF_AHI + ACH)
#define OFF_BHI  (OFF_ALO + ACH)
#define OFF_BLO  (OFF_BHI + ACH)
#define PROJ_SMEM (OFF_BLO + ACH)   // 110592 -> 2 CTAs = 216KB
// epilogue reuse (all chunk buffers dead):
#define OFF_KB OFF_STAGE            // [64][132] floats = 33792
#define OFF_VB OFF_AHI              // [128][68] floats = 34816

__global__ __launch_bounds__(512, 2) void proj_mma_kernel(const float* __restrict__ feat) {
    extern __shared__ char smem[];
    uint32_t sbase = smem_u32(smem);
    int t = threadIdx.x, wid = t >> 5, lane = t & 31;
    int wm = wid >> 2, wn = wid & 3;   // warp grid 4(M) x 4(N); warp tile 32x32
    float* mr = (float*)(smem + OFF_MR);
    float* c1s = (float*)(smem + OFF_C1);
    float* c2s = (float*)(smem + OFF_C2);

    if (t < 128) { c1s[t] = g_c1[t]; c2s[t] = g_c2[t]; }

    int row = t >> 2, seg = t & 3;                  // thread owns stage[row][seg*16..+15]
    const float* gsrc = feat + (size_t)blockIdx.x * 128 * FEAT + row * FEAT + seg * 16;
    uint32_t sstage = sbase + OFF_STAGE + (uint32_t)row * STG + (uint32_t)seg * 64;

    // preload chunk 0
#pragma unroll
    for (int j = 0; j < 4; j++) cp_async16(sstage + j * 16, gsrc + j * 4);
    cp_commit();

    float runs = 0.f, runq = 0.f;
    float acc[2][4][4];
#pragma unroll
    for (int a = 0; a < 2; a++)
#pragma unroll
        for (int b = 0; b < 4; b++)
#pragma unroll
            for (int c = 0; c < 4; c++) acc[a][b][c] = 0.f;

    int arow = wm * 32 + (lane & 15);
    int akh = (lane >> 4) * 8;
    int bg = lane >> 3;
    int brow = wn * 32 + ((bg >> 1) * 8) + (lane & 7);
    int bkh = (bg & 1) * 8;

    for (int c = 0; c < 4; c++) {
        cp_wait0();
        __syncthreads();    // stage has chunk c; A/B consumers of chunk c-1 done
        // read own 16 floats from stage
        float4 x[4];
#pragma unroll
        for (int j = 0; j < 4; j++)
            x[j] = *(float4*)(smem + OFF_STAGE + row * STG + seg * 64 + j * 16);
        // prefetch chunk c+1 into own (now-free) slots
        if (c < 3) {
#pragma unroll
            for (int j = 0; j < 4; j++)
                cp_async16(sstage + j * 16, gsrc + (c + 1) * 64 + j * 4);
            cp_commit();
        }
        // stats + hi/lo split into A buffers
#pragma unroll
        for (int j = 0; j < 4; j++) {
            float4 v = x[j];
            runs += v.x + v.y + v.z + v.w;
            runq += v.x * v.x + v.y * v.y + v.z * v.z + v.w * v.w;
            __nv_bfloat16 h0 = __float2bfloat16(v.x), h1 = __float2bfloat16(v.y);
            __nv_bfloat16 h2 = __float2bfloat16(v.z), h3 = __float2bfloat16(v.w);
            __nv_bfloat16 l0 = __float2bfloat16(v.x - __bfloat162float(h0));
            __nv_bfloat16 l1 = __float2bfloat16(v.y - __bfloat162float(h1));
            __nv_bfloat16 l2 = __float2bfloat16(v.z - __bfloat162float(h2));
            __nv_bfloat16 l3 = __float2bfloat16(v.w - __bfloat162float(h3));
            uint2 hw, lw;
            hw.x = (uint32_t)__bfloat16_as_ushort(h0) | ((uint32_t)__bfloat16_as_ushort(h1) << 16);
            hw.y = (uint32_t)__bfloat16_as_ushort(h2) | ((uint32_t)__bfloat16_as_ushort(h3) << 16);
            lw.x = (uint32_t)__bfloat16_as_ushort(l0) | ((uint32_t)__bfloat16_as_ushort(l1) << 16);
            lw.y = (uint32_t)__bfloat16_as_ushort(l2) | ((uint32_t)__bfloat16_as_ushort(l3) << 16);
            unsigned off = (unsigned)row * PST + (unsigned)(seg * 16 + j * 4) * 2u;
            *(uint2*)(smem + OFF_AHI + off) = hw;
            *(uint2*)(smem + OFF_ALO + off) = lw;
        }
        // B chunk copy (L2-resident)
#pragma unroll
        for (int rep = 0; rep < 2; rep++) {
            int i = t + rep * 512;
            int n = i >> 3, j = i & 7;
            unsigned so = (unsigned)n * PST + (unsigned)j * 16u;
            *(uint4*)(smem + OFF_BHI + so) = *(const uint4*)(g_Whi + n * 256 + c * 64 + j * 8);
            *(uint4*)(smem + OFF_BLO + so) = *(const uint4*)(g_Wlo + n * 256 + c * 64 + j * 8);
        }
        __syncthreads();

#pragma unroll
        for (int ks = 0; ks < 4; ks++) {
            int kb = ks * 16;
            uint32_t ah[2][4], al[2][4], bh[2][4], bl[2][4];
#pragma unroll
            for (int mi = 0; mi < 2; mi++) {
                uint32_t ao = sbase + (uint32_t)((arow + mi * 16) * PST + (kb + akh) * 2);
                ldsm_x4(ah[mi], ao + OFF_AHI);
                ldsm_x4(al[mi], ao + OFF_ALO);
            }
#pragma unroll
            for (int p = 0; p < 2; p++) {
                uint32_t bo = sbase + (uint32_t)((brow + p * 16) * PST + (kb + bkh) * 2);
                ldsm_x4(bh[p], bo + OFF_BHI);
                ldsm_x4(bl[p], bo + OFF_BLO);
            }
#pragma unroll
            for (int mi = 0; mi < 2; mi++)
#pragma unroll
                for (int ni = 0; ni < 4; ni++) {
                    int p = ni >> 1, rp = (ni & 1) * 2;
                    mma_bf16(acc[mi][ni], ah[mi], bh[p][rp], bh[p][rp + 1]);
                    mma_bf16(acc[mi][ni], ah[mi], bl[p][rp], bl[p][rp + 1]);
                    mma_bf16(acc[mi][ni], al[mi], bh[p][rp], bh[p][rp + 1]);
                }
        }
    }

    // finalize LN stats (4 threads per row)
    runs += __shfl_xor_sync(0xffffffffu, runs, 1);
    runq += __shfl_xor_sync(0xffffffffu, runq, 1);
    runs += __shfl_xor_sync(0xffffffffu, runs, 2);
    runq += __shfl_xor_sync(0xffffffffu, runq, 2);
    if (seg == 0) {
        float m = runs * (1.f / 256.f);
        float var = runq * (1.f / 256.f) - m * m;
        mr[row * 2] = m;
        mr[row * 2 + 1] = rsqrtf(var + 1e-5f);
    }
    __syncthreads();   // mr ready; all chunk buffers dead -> reuse as kbuf/vbuf

    float* kbuf = (float*)(smem + OFF_KB);   // [64 d][132]
    float* vbuf = (float*)(smem + OFF_VB);   // [128 tok][68]
    int qr = lane >> 2, qc = lane & 3;
#pragma unroll
    for (int mi = 0; mi < 2; mi++) {
        int lrow = wm * 32 + mi * 16 + qr;
        float m0 = mr[lrow * 2], r0 = mr[lrow * 2 + 1];
        float m1 = mr[(lrow + 8) * 2], r1 = mr[(lrow + 8) * 2 + 1];
#pragma unroll
        for (int ni = 0; ni < 4; ni++) {
            int n = wn * 32 + ni * 8 + 2 * qc;
            float C1a = c1s[n], C2a = c2s[n], C1b = c1s[n + 1], C2b = c2s[n + 1];
            float v00 = fmaf(r0, acc[mi][ni][0], fmaf(-m0 * r0, C2a, C1a));
            float v01 = fmaf(r0, acc[mi][ni][1], fmaf(-m0 * r0, C2b, C1b));
            float v10 = fmaf(r1, acc[mi][ni][2], fmaf(-m1 * r1, C2a, C1a));
            float v11 = fmaf(r1, acc[mi][ni][3], fmaf(-m1 * r1, C2b, C1b));
            if (n < 64) {
                kbuf[n * 132 + lrow] = v00;
                kbuf[n * 132 + lrow + 8] = v10;
                kbuf[(n + 1) * 132 + lrow] = v01;
                kbuf[(n + 1) * 132 + lrow + 8] = v11;
            } else {
                int hh = n - 64;
                *(float2*)(vbuf + lrow * 68 + hh) = make_float2(v00, v01);
                *(float2*)(vbuf + (lrow + 8) * 68 + hh) = make_float2(v10, v11);
            }
        }
    }
    __syncthreads();

    // coalesced stores
    unsigned tok0 = blockIdx.x * 128u;
    unsigned bidx = tok0 >> 12;
    unsigned np = tok0 & 4095u;
    float* kdst = g_kT + (size_t)bidx * (SD * NN) + np;
#pragma unroll
    for (int rep = 0; rep < 4; rep++) {
        int i = t + rep * 512;
        int d = i >> 5, g = i & 31;
        *(float4*)(kdst + (size_t)d * NN + g * 4) = *(float4*)(kbuf + d * 132 + g * 4);
    }
    float* vdst = g_v + (size_t)tok0 * SD;
#pragma unroll
    for (int rep = 0; rep < 4; rep++) {
        int i = t + rep * 512;
        int tok = i >> 4, g = i & 15;
        *(float4*)(vdst + (size_t)tok * SD + g * 4) = *(float4*)(vbuf + tok * 68 + g * 4);
    }
}

// ---------------- kernel 3: attention pass, gmem-direct k/v (256 thr, 512 n per block) ----------------
__global__ __launch_bounds__(256, 4) void attn_kernel() {
    __shared__ float qs[384];
    __shared__ float lgp[2 * NS * 512];   // partial logits; reused as pUw[8][NS][64]
    __shared__ float att[NS * 512];
    __shared__ float srw[4 * NS];

    int t = threadIdx.x;
    int b = blockIdx.x >> 3;
    int chunk = blockIdx.x & 7;
    int w = t >> 5, lane = t & 31;
    int dh = t >> 7;            // warps 0-3: d 0..31, warps 4-7: d 32..63
    int nq = t & 127;           // float4 group of n

    const float* kTb = g_kT + (size_t)b * (SD * NN) + chunk * 512;
    const float* vB = g_v + ((size_t)b * NN + chunk * 512) * SD;

    for (int i = t; i < 384; i += 256) qs[i] = g_q[b * 384 + i];
    __syncthreads();

    // phase 1: partial logits over the thread's d-half, 4 n per thread
    float4 lg[NS];
#pragma unroll
    for (int s = 0; s < NS; s++) lg[s] = make_float4(0.f, 0.f, 0.f, 0.f);
#pragma unroll 4
    for (int i = 0; i < 32; i++) {
        int d = dh * 32 + i;
        float4 k4 = *(const float4*)(kTb + (size_t)d * NN + nq * 4);
#pragma unroll
        for (int s = 0; s < NS; s++) {
            float qv = qs[s * 64 + d];
            lg[s].x += qv * k4.x;
            lg[s].y += qv * k4.y;
            lg[s].z += qv * k4.z;
            lg[s].w += qv * k4.w;
        }
    }
#pragma unroll
    for (int s = 0; s < NS; s++)
        *(float4*)(lgp + (dh * NS + s) * 512 + nq * 4) = lg[s];
    __syncthreads();

    // phase 2: combine halves + softmax over slots (threads 0-127, 4 n each)
    float sred[NS] = {0.f, 0.f, 0.f, 0.f, 0.f, 0.f};
    if (t < 128) {
        float lv[NS][4];
#pragma unroll
        for (int s = 0; s < NS; s++) {
            float4 a = *(const float4*)(lgp + s * 512 + t * 4);
            float4 bq = *(const float4*)(lgp + (NS + s) * 512 + t * 4);
            lv[s][0] = (a.x + bq.x) * 0.125f;
            lv[s][1] = (a.y + bq.y) * 0.125f;
            lv[s][2] = (a.z + bq.z) * 0.125f;
            lv[s][3] = (a.w + bq.w) * 0.125f;
        }
        float av[NS][4];
#pragma unroll
        for (int e = 0; e < 4; e++) {
            float mx = -1e30f;
#pragma unroll
            for (int s = 0; s < NS; s++) mx = fmaxf(mx, lv[s][e]);
            float den = 0.f;
#pragma unroll
            for (int s = 0; s < NS; s++) { av[s][e] = expf(lv[s][e] - mx); den += av[s][e]; }
            float inv = 1.f / den;
#pragma unroll
            for (int s = 0; s < NS; s++) { av[s][e] *= inv; sred[s] += av[s][e]; }
        }
#pragma unroll
        for (int s = 0; s < NS; s++)
            *(float4*)(att + s * 512 + t * 4) = make_float4(av[s][0], av[s][1], av[s][2], av[s][3]);
    }
    __syncthreads();

    // phase 3: updates; warp owns 64 n, lane owns h-quad, 2 n per iteration
    float accU[NS][4];
#pragma unroll
    for (int s = 0; s < NS; s++)
#pragma unroll
        for (int e = 0; e < 4; e++) accU[s][e] = 0.f;
    int nsub = lane >> 4;
    int h4 = (lane & 15) * 4;
#pragma unroll 4
    for (int i = 0; i < 32; i++) {
        int n = w * 64 + 2 * i + nsub;
        float4 v4 = *(const float4*)(vB + (size_t)n * SD + h4);
#pragma unroll
        for (int s = 0; s < NS; s++) {
            float a = att[s * 512 + n];
            accU[s][0] += a * v4.x;
            accU[s][1] += a * v4.y;
            accU[s][2] += a * v4.z;
            accU[s][3] += a * v4.w;
        }
    }
#pragma unroll
    for (int s = 0; s < NS; s++)
#pragma unroll
        for (int e = 0; e < 4; e++)
            accU[s][e] += __shfl_xor_sync(0xffffffffu, accU[s][e], 16);
    float* pUw = lgp;   // lgp is dead now
    if (lane < 16) {
#pragma unroll
        for (int s = 0; s < NS; s++)
            *(float4*)(pUw + (w * NS + s) * 64 + h4) =
                make_float4(accU[s][0], accU[s][1], accU[s][2], accU[s][3]);
    }
    if (t < 128) {
#pragma unroll
        for (int s = 0; s < NS; s++) {
            float v = sred[s];
#pragma unroll
            for (int o = 16; o; o >>= 1) v += __shfl_xor_sync(0xffffffffu, v, o);
            if (lane == 0) srw[w * NS + s] = v;
        }
    }
    __syncthreads();

    for (int idx = t; idx < NS * SD; idx += 256) {
        int s = idx >> 6, h = idx & 63;
        float sum = 0.f;
#pragma unroll
        for (int w2 = 0; w2 < 8; w2++) sum += pUw[(w2 * NS + s) * 64 + h];
        g_pU[(((size_t)b * NCHUNK + chunk) * NS + s) * SD + h] = sum;
    }
    if (t < NS) {
        float ss = srw[t] + srw[NS + t] + srw[2 * NS + t] + srw[3 * NS + t];
        g_pS[((unsigned)b * NCHUNK + chunk) * NS + t] = ss;
    }
}

// ---------------- kernel 4: combine + GRU + MLP + LN + q (one batch per block) ----------------
__global__ __launch_bounds__(384) void update_kernel(const float* __restrict__ b_ih,
                                                     const float* __restrict__ b_hh,
                                                     const float* __restrict__ ln_mlp_g,
                                                     const float* __restrict__ ln_mlp_b,
                                                     const float* __restrict__ ln_slot_g,
                                                     const float* __restrict__ ln_slot_b,
                                                     const float* __restrict__ mlp_b1,
                                                     const float* __restrict__ mlp_b2,
                                                     float* __restrict__ out, int last) {
    __shared__ float S[NS];
    __shared__ float prev[NS * SD];
    __shared__ float upd[NS * SD];
    __shared__ float gi[NS * 192];
    __shared__ float gh[NS * 192];
    __shared__ float mln[NS * SD];
    __shared__ float m1[NS * 128];
    __shared__ float red[12][2];

    int b = blockIdx.x;
    int t = threadIdx.x;
    int s = t >> 6, h = t & 63;
    int wid = t >> 5, lane = t & 31;

    float u = 0.f;
#pragma unroll
    for (int c = 0; c < NCHUNK; c++)
        u += g_pU[(((unsigned)b * NCHUNK + c) * NS + s) * SD + h];
    if (h == 0) {
        float ss = 0.f;
#pragma unroll
        for (int c = 0; c < NCHUNK; c++) ss += g_pS[((unsigned)b * NCHUNK + c) * NS + s];
        S[s] = ss;
    }
    prev[t] = g_slots[b * 384 + t];
    __syncthreads();
    upd[t] = u / (S[s] + 1e-8f);
    __syncthreads();

#pragma unroll
    for (int g = 0; g < 6; g++) {
        int idx = t + g * 384;
        int half = idx / 1152;
        int r = idx - half * 1152;
        int s2 = r / 192, c = r - s2 * 192;
        const float* src = half ? prev : upd;
        const float* wT = half ? g_WhhT : g_WihT;
        float acc = half ? b_hh[c] : b_ih[c];
#pragma unroll
        for (int hh = 0; hh < SD; hh++) acc += src[s2 * SD + hh] * wT[hh * 192 + c];
        if (half) gh[s2 * 192 + c] = acc; else gi[s2 * 192 + c] = acc;
    }
    __syncthreads();

    float ir = gi[s * 192 + h], iz = gi[s * 192 + 64 + h], inn = gi[s * 192 + 128 + h];
    float hr = gh[s * 192 + h], hz = gh[s * 192 + 64 + h], hn = gh[s * 192 + 128 + h];
    float rg = 1.f / (1.f + expf(-(ir + hr)));
    float zg = 1.f / (1.f + expf(-(iz + hz)));
    float ng = tanhf(inn + rg * hn);
    float hv = (1.f - zg) * ng + zg * prev[t];

    {
        float sum = hv, sq = hv * hv;
        warp_red2(sum, sq);
        if (lane == 0) { red[wid][0] = sum; red[wid][1] = sq; }
    }
    __syncthreads();
    {
        float tsum = red[2 * s][0] + red[2 * s + 1][0];
        float tsq = red[2 * s][1] + red[2 * s + 1][1];
        float m = tsum * (1.f / 64.f);
        float var = tsq * (1.f / 64.f) - m * m;
        float rstd = rsqrtf(var + 1e-5f);
        mln[t] = (hv - m) * rstd * ln_mlp_g[h] + ln_mlp_b[h];
    }
    __syncthreads();

#pragma unroll
    for (int g = 0; g < 2; g++) {
        int idx = t + g * 384;
        int s2 = idx >> 7, c = idx & 127;
        float acc = mlp_b1[c];
#pragma unroll
        for (int hh = 0; hh < SD; hh++) acc += mln[s2 * SD + hh] * g_W1T[hh * 128 + c];
        m1[s2 * 128 + c] = fmaxf(acc, 0.f);
    }
    __syncthreads();

    float acc2 = mlp_b2[h];
#pragma unroll
    for (int c = 0; c < 128; c++) acc2 += m1[s * 128 + c] * g_W2T[c * SD + h];
    float snew = hv + acc2;
    g_slots[b * 384 + t] = snew;
    if (last) {
        out[b * 384 + t] = snew;
    } else {
        __syncthreads();
        {
            float sum = snew, sq = snew * snew;
            warp_red2(sum, sq);
            if (lane == 0) { red[wid][0] = sum; red[wid][1] = sq; }
        }
        __syncthreads();
        {
            float tsum = red[2 * s][0] + red[2 * s + 1][0];
            float tsq = red[2 * s][1] + red[2 * s + 1][1];
            float m = tsum * (1.f / 64.f);
            float var = tsq * (1.f / 64.f) - m * m;
            float rstd = rsqrtf(var + 1e-5f);
            mln[t] = (snew - m) * rstd * ln_slot_g[h] + ln_slot_b[h];
        }
        __syncthreads();
        float qv = 0.f;
#pragma unroll
        for (int hh = 0; hh < SD; hh++) qv += mln[s * SD + hh] * g_WqT[hh * SD + h];
        g_q[b * 384 + t] = qv;
    }
}

// ---------------- launch ----------------
extern "C" void kernel_launch(void* const* d_in, const int* in_sizes, int n_in,
                              void* d_out, int out_size) {
    const float* features   = (const float*)d_in[0];
    const float* slot_noise = (const float*)d_in[1];
    const float* slot_mu    = (const float*)d_in[2];
    const float* slot_sigma = (const float*)d_in[3];
    const float* ln_feat_g  = (const float*)d_in[4];
    const float* ln_feat_b  = (const float*)d_in[5];
    const float* ln_slot_g  = (const float*)d_in[6];
    const float* ln_slot_b  = (const float*)d_in[7];
    const float* ln_mlp_g   = (const float*)d_in[8];
    const float* ln_mlp_b   = (const float*)d_in[9];
    const float* Wk         = (const float*)d_in[10];
    const float* Wv         = (const float*)d_in[11];
    const float* Wq         = (const float*)d_in[12];
    const float* W_ih       = (const float*)d_in[13];
    const float* W_hh       = (const float*)d_in[14];
    const float* b_ih       = (const float*)d_in[15];
    const float* b_hh       = (const float*)d_in[16];
    const float* mlp_W1     = (const float*)d_in[17];
    const float* mlp_b1     = (const float*)d_in[18];
    const float* mlp_W2     = (const float*)d_in[19];
    const float* mlp_b2     = (const float*)d_in[20];
    float* out = (float*)d_out;

    cudaFuncSetAttribute(proj_mma_kernel, cudaFuncAttributeMaxDynamicSharedMemorySize, PROJ_SMEM);

    transpose_kernel<<<64, 256>>>(Wk, Wv, Wq, W_ih, W_hh, mlp_W1, mlp_W2, ln_feat_g, ln_feat_b);
    init_kernel<<<BB, 384>>>(slot_noise, slot_mu, slot_sigma, ln_slot_g, ln_slot_b);
    proj_mma_kernel<<<2048, 512, PROJ_SMEM>>>(features);
    for (int it = 0; it < 3; it++) {
        attn_kernel<<<BB * NCHUNK, 256>>>();
        update_kernel<<<BB, 384>>>(b_ih, b_hh, ln_mlp_g, ln_mlp_b, ln_slot_g, ln_slot_b,
                                   mlp_b1, mlp_b2, out, it == 2);
    }
}

// round 9
// speedup vs baseline: 2.8139x; 1.2216x over previous
#include <cuda_runtime.h>
#include <cuda_bf16.h>
#include <cuda_fp16.h>
#include <math.h>
#include <stdint.h>

#define BB 64
#define NN 4096
#define FEAT 256
#define NS 6
#define SD 64
#define NCHUNK 8

// ---------------- scratch (device globals: no allocs allowed) ----------------
__device__ float g_kT[BB * SD * NN];         // 64 MB  [b][d][n]
__device__ float g_v[BB * NN * SD];          // 64 MB  [b*n][h]
__device__ __half g_Whf[128 * 256];          // (W*g) fp16  [n][k]
__device__ float g_c1[128];                  // W @ ln_feat_b
__device__ float g_c2[128];                  // W @ ln_feat_g
__device__ float g_WqT[SD * SD];
__device__ float g_WihT[SD * 192];
__device__ float g_WhhT[SD * 192];
__device__ float g_W1T[SD * 128];
__device__ float g_W2T[128 * SD];
__device__ float g_slots[BB * NS * SD];
__device__ float g_q[BB * NS * SD];
__device__ float g_pU[BB * NCHUNK * NS * SD];
__device__ float g_pS[BB * NCHUNK * NS];

__device__ __forceinline__ void warp_red2(float& a, float& b) {
#pragma unroll
    for (int o = 16; o; o >>= 1) {
        a += __shfl_xor_sync(0xffffffffu, a, o);
        b += __shfl_xor_sync(0xffffffffu, b, o);
    }
}

__device__ __forceinline__ uint32_t smem_u32(const void* p) {
    uint32_t a;
    asm("{ .reg .u64 t; cvta.to.shared.u64 t, %1; cvt.u32.u64 %0, t; }" : "=r"(a) : "l"(p));
    return a;
}

__device__ __forceinline__ void ldsm_x4(uint32_t* r, uint32_t addr) {
    asm volatile("ldmatrix.sync.aligned.m8n8.x4.shared.b16 {%0,%1,%2,%3}, [%4];"
                 : "=r"(r[0]), "=r"(r[1]), "=r"(r[2]), "=r"(r[3]) : "r"(addr));
}

__device__ __forceinline__ void mma_f16(float* c, const uint32_t* a, uint32_t b0, uint32_t b1) {
    asm volatile(
        "mma.sync.aligned.m16n8k16.row.col.f32.f16.f16.f32 "
        "{%0,%1,%2,%3}, {%4,%5,%6,%7}, {%8,%9}, {%0,%1,%2,%3};"
        : "+f"(c[0]), "+f"(c[1]), "+f"(c[2]), "+f"(c[3])
        : "r"(a[0]), "r"(a[1]), "r"(a[2]), "r"(a[3]), "r"(b0), "r"(b1));
}

// ---------------- kernel 0: stage weights ----------------
__global__ void transpose_kernel(const float* __restrict__ Wk, const float* __restrict__ Wv,
                                 const float* __restrict__ Wq, const float* __restrict__ Wih,
                                 const float* __restrict__ Whh, const float* __restrict__ W1,
                                 const float* __restrict__ W2, const float* __restrict__ lfg,
                                 const float* __restrict__ lfb) {
    int tid = blockIdx.x * 256 + threadIdx.x;
    const int stride = 64 * 256;
    for (int idx = tid; idx < 128 * 256; idx += stride) {
        int n = idx >> 8, k = idx & 255;
        float w = ((n < 64) ? Wk[n * FEAT + k] : Wv[(n - 64) * FEAT + k]) * lfg[k];
        g_Whf[idx] = __float2half_rn(w);
    }
    if (blockIdx.x == 0) {
        int t = threadIdx.x;
        int n = t & 127;
        const float* Wr = (n < 64) ? (Wk + n * FEAT) : (Wv + (n - 64) * FEAT);
        const float* vec = (t < 128) ? lfb : lfg;
        float acc = 0.f;
        for (int k = 0; k < 256; k++) acc += Wr[k] * vec[k];
        if (t < 128) g_c1[n] = acc; else g_c2[n] = acc;
    }
    for (int idx = tid; idx < SD * SD; idx += stride) {
        int h = idx >> 6, g = idx & 63;
        g_WqT[idx] = Wq[g * SD + h];
    }
    for (int idx = tid; idx < SD * 192; idx += stride) {
        int h = idx / 192, c = idx % 192;
        g_WihT[idx] = Wih[c * SD + h];
        g_WhhT[idx] = Whh[c * SD + h];
    }
    for (int idx = tid; idx < SD * 128; idx += stride) {
        int h = idx >> 7, c = idx & 127;
        g_W1T[idx] = W1[c * SD + h];
    }
    for (int idx = tid; idx < 128 * SD; idx += stride) {
        int c = idx >> 6, h = idx & 63;
        g_W2T[idx] = W2[h * 128 + c];
    }
}

// ---------------- kernel 1: slots init + q0 ----------------
__global__ __launch_bounds__(384) void init_kernel(const float* __restrict__ noise,
                                                   const float* __restrict__ mu,
                                                   const float* __restrict__ sigma,
                                                   const float* __restrict__ lng,
                                                   const float* __restrict__ lnb) {
    __shared__ float sln[NS * SD];
    __shared__ float red[12][2];
    int b = blockIdx.x;
    int t = threadIdx.x;
    int s = t >> 6, h = t & 63;
    int wid = t >> 5, lane = t & 31;

    float sv = mu[h] + sigma[h] * noise[b * 384 + t];
    g_slots[b * 384 + t] = sv;

    float sum = sv, sq = sv * sv;
    warp_red2(sum, sq);
    if (lane == 0) { red[wid][0] = sum; red[wid][1] = sq; }
    __syncthreads();
    float tsum = red[2 * s][0] + red[2 * s + 1][0];
    float tsq = red[2 * s][1] + red[2 * s + 1][1];
    float m = tsum * (1.f / 64.f);
    float var = tsq * (1.f / 64.f) - m * m;
    float rstd = rsqrtf(var + 1e-5f);
    sln[t] = (sv - m) * rstd * lng[h] + lnb[h];
    __syncthreads();
    float qv = 0.f;
#pragma unroll
    for (int hh = 0; hh < SD; hh++) qv += sln[s * SD + hh] * g_WqT[hh * SD + h];
    g_q[b * 384 + t] = qv;
}

// ---------------- kernel 2: K/V projection, fp16 single-term, 2 K-chunks ----------------
#define PST 272                     // bytes per row (128 fp16 + 16 pad)
#define ACH (128 * PST)             // 34816
#define OFF_MR  0                   // [128][2] floats
#define OFF_C1  1024
#define OFF_C2  1536
#define OFF_A   2048
#define OFF_B   (OFF_A + ACH)
#define PROJ_SMEM (OFF_B + ACH)     // 71680 -> 2 CTAs/SM
// epilogue reuse:
#define OFF_KB OFF_A                // [64][132] floats = 33792
#define OFF_VB OFF_B                // [128][68] floats = 34816

__global__ __launch_bounds__(512, 2) void proj_mma_kernel(const float* __restrict__ feat) {
    extern __shared__ char smem[];
    uint32_t sbase = smem_u32(smem);
    int t = threadIdx.x, wid = t >> 5, lane = t & 31;
    int wm = wid >> 2, wn = wid & 3;   // warp grid 4(M) x 4(N); warp tile 32x32
    float* mr = (float*)(smem + OFF_MR);
    float* c1s = (float*)(smem + OFF_C1);
    float* c2s = (float*)(smem + OFF_C2);

    if (t < 128) { c1s[t] = g_c1[t]; c2s[t] = g_c2[t]; }

    int row = t >> 2, seg = t & 3;                  // thread owns 32 floats per chunk
    const float* gsrc = feat + (size_t)blockIdx.x * 128 * FEAT + row * FEAT + seg * 32;
    float runs = 0.f, runq = 0.f;

    float acc[2][4][4];
#pragma unroll
    for (int a = 0; a < 2; a++)
#pragma unroll
        for (int b = 0; b < 4; b++)
#pragma unroll
            for (int c = 0; c < 4; c++) acc[a][b][c] = 0.f;

    int arow = wm * 32 + (lane & 15);
    int akh = (lane >> 4) * 8;
    int bg = lane >> 3;
    int brow = wn * 32 + ((bg >> 1) * 8) + (lane & 7);
    int bkh = (bg & 1) * 8;

    for (int c = 0; c < 2; c++) {
        __syncthreads();    // consumers of prior chunk done
        // A chunk: 32 raw floats -> stats + fp16, direct LDG
#pragma unroll
        for (int j = 0; j < 8; j++) {
            float4 x = *(const float4*)(gsrc + c * 128 + j * 4);
            runs += x.x + x.y + x.z + x.w;
            runq += x.x * x.x + x.y * x.y + x.z * x.z + x.w * x.w;
            __half2 p0 = __floats2half2_rn(x.x, x.y);
            __half2 p1 = __floats2half2_rn(x.z, x.w);
            uint2 hw;
            hw.x = *(uint32_t*)&p0;
            hw.y = *(uint32_t*)&p1;
            unsigned off = (unsigned)row * PST + (unsigned)(seg * 32 + j * 4) * 2u;
            *(uint2*)(smem + OFF_A + off) = hw;
        }
        // B chunk (L2-resident), 128 rows x 128 fp16
#pragma unroll
        for (int rep = 0; rep < 4; rep++) {
            int i = t + rep * 512;
            int n = i >> 4, j = i & 15;
            *(uint4*)(smem + OFF_B + (unsigned)n * PST + (unsigned)j * 16u) =
                *(const uint4*)(g_Whf + n * 256 + c * 128 + j * 8);
        }
        __syncthreads();

#pragma unroll
        for (int ks = 0; ks < 8; ks++) {
            int kb = ks * 16;
            uint32_t af[2][4], bf[2][4];
#pragma unroll
            for (int mi = 0; mi < 2; mi++)
                ldsm_x4(af[mi], sbase + OFF_A + (uint32_t)((arow + mi * 16) * PST + (kb + akh) * 2));
#pragma unroll
            for (int p = 0; p < 2; p++)
                ldsm_x4(bf[p], sbase + OFF_B + (uint32_t)((brow + p * 16) * PST + (kb + bkh) * 2));
#pragma unroll
            for (int mi = 0; mi < 2; mi++)
#pragma unroll
                for (int ni = 0; ni < 4; ni++) {
                    int p = ni >> 1, rp = (ni & 1) * 2;
                    mma_f16(acc[mi][ni], af[mi], bf[p][rp], bf[p][rp + 1]);
                }
        }
    }

    // finalize LN stats (4 threads per row, aligned groups)
    runs += __shfl_xor_sync(0xffffffffu, runs, 1);
    runq += __shfl_xor_sync(0xffffffffu, runq, 1);
    runs += __shfl_xor_sync(0xffffffffu, runs, 2);
    runq += __shfl_xor_sync(0xffffffffu, runq, 2);
    if (seg == 0) {
        float m = runs * (1.f / 256.f);
        float var = runq * (1.f / 256.f) - m * m;
        mr[row * 2] = m;
        mr[row * 2 + 1] = rsqrtf(var + 1e-5f);
    }
    __syncthreads();   // mr ready; chunk buffers dead -> reuse as kbuf/vbuf

    float* kbuf = (float*)(smem + OFF_KB);   // [64 d][132]
    float* vbuf = (float*)(smem + OFF_VB);   // [128 tok][68]
    int qr = lane >> 2, qc = lane & 3;
#pragma unroll
    for (int mi = 0; mi < 2; mi++) {
        int lrow = wm * 32 + mi * 16 + qr;
        float m0 = mr[lrow * 2], r0 = mr[lrow * 2 + 1];
        float m1 = mr[(lrow + 8) * 2], r1 = mr[(lrow + 8) * 2 + 1];
#pragma unroll
        for (int ni = 0; ni < 4; ni++) {
            int n = wn * 32 + ni * 8 + 2 * qc;
            float C1a = c1s[n], C2a = c2s[n], C1b = c1s[n + 1], C2b = c2s[n + 1];
            float v00 = fmaf(r0, acc[mi][ni][0], fmaf(-m0 * r0, C2a, C1a));
            float v01 = fmaf(r0, acc[mi][ni][1], fmaf(-m0 * r0, C2b, C1b));
            float v10 = fmaf(r1, acc[mi][ni][2], fmaf(-m1 * r1, C2a, C1a));
            float v11 = fmaf(r1, acc[mi][ni][3], fmaf(-m1 * r1, C2b, C1b));
            if (n < 64) {
                kbuf[n * 132 + lrow] = v00;
                kbuf[n * 132 + lrow + 8] = v10;
                kbuf[(n + 1) * 132 + lrow] = v01;
                kbuf[(n + 1) * 132 + lrow + 8] = v11;
            } else {
                int hh = n - 64;
                *(float2*)(vbuf + lrow * 68 + hh) = make_float2(v00, v01);
                *(float2*)(vbuf + (lrow + 8) * 68 + hh) = make_float2(v10, v11);
            }
        }
    }
    __syncthreads();

    // coalesced stores
    unsigned tok0 = blockIdx.x * 128u;
    unsigned bidx = tok0 >> 12;
    unsigned np = tok0 & 4095u;
    float* kdst = g_kT + (size_t)bidx * (SD * NN) + np;
#pragma unroll
    for (int rep = 0; rep < 4; rep++) {
        int i = t + rep * 512;
        int d = i >> 5, g = i & 31;
        *(float4*)(kdst + (size_t)d * NN + g * 4) = *(float4*)(kbuf + d * 132 + g * 4);
    }
    float* vdst = g_v + (size_t)tok0 * SD;
#pragma unroll
    for (int rep = 0; rep < 4; rep++) {
        int i = t + rep * 512;
        int tok = i >> 4, g = i & 15;
        *(float4*)(vdst + (size_t)tok * SD + g * 4) = *(float4*)(vbuf + tok * 68 + g * 4);
    }
}

// ---------------- kernel 3: attention pass, gmem-direct k/v (256 thr, 512 n per block) ----------------
__global__ __launch_bounds__(256, 4) void attn_kernel() {
    __shared__ float qs[384];
    __shared__ float lgp[2 * NS * 512];   // partial logits; reused as pUw[8][NS][64]
    __shared__ float att[NS * 512];
    __shared__ float srw[4 * NS];

    int t = threadIdx.x;
    int b = blockIdx.x >> 3;
    int chunk = blockIdx.x & 7;
    int w = t >> 5, lane = t & 31;
    int dh = t >> 7;            // warps 0-3: d 0..31, warps 4-7: d 32..63
    int nq = t & 127;           // float4 group of n

    const float* kTb = g_kT + (size_t)b * (SD * NN) + chunk * 512;
    const float* vB = g_v + ((size_t)b * NN + chunk * 512) * SD;

    for (int i = t; i < 384; i += 256) qs[i] = g_q[b * 384 + i];
    __syncthreads();

    // phase 1: partial logits over the thread's d-half, 4 n per thread
    float4 lg[NS];
#pragma unroll
    for (int s = 0; s < NS; s++) lg[s] = make_float4(0.f, 0.f, 0.f, 0.f);
#pragma unroll 4
    for (int i = 0; i < 32; i++) {
        int d = dh * 32 + i;
        float4 k4 = *(const float4*)(kTb + (size_t)d * NN + nq * 4);
#pragma unroll
        for (int s = 0; s < NS; s++) {
            float qv = qs[s * 64 + d];
            lg[s].x += qv * k4.x;
            lg[s].y += qv * k4.y;
            lg[s].z += qv * k4.z;
            lg[s].w += qv * k4.w;
        }
    }
#pragma unroll
    for (int s = 0; s < NS; s++)
        *(float4*)(lgp + (dh * NS + s) * 512 + nq * 4) = lg[s];
    __syncthreads();

    // phase 2: combine halves + softmax over slots (threads 0-127, 4 n each)
    float sred[NS] = {0.f, 0.f, 0.f, 0.f, 0.f, 0.f};
    if (t < 128) {
        float lv[NS][4];
#pragma unroll
        for (int s = 0; s < NS; s++) {
            float4 a = *(const float4*)(lgp + s * 512 + t * 4);
            float4 bq = *(const float4*)(lgp + (NS + s) * 512 + t * 4);
            lv[s][0] = (a.x + bq.x) * 0.125f;
            lv[s][1] = (a.y + bq.y) * 0.125f;
            lv[s][2] = (a.z + bq.z) * 0.125f;
            lv[s][3] = (a.w + bq.w) * 0.125f;
        }
        float av[NS][4];
#pragma unroll
        for (int e = 0; e < 4; e++) {
            float mx = -1e30f;
#pragma unroll
            for (int s = 0; s < NS; s++) mx = fmaxf(mx, lv[s][e]);
            float den = 0.f;
#pragma unroll
            for (int s = 0; s < NS; s++) { av[s][e] = expf(lv[s][e] - mx); den += av[s][e]; }
            float inv = 1.f / den;
#pragma unroll
            for (int s = 0; s < NS; s++) { av[s][e] *= inv; sred[s] += av[s][e]; }
        }
#pragma unroll
        for (int s = 0; s < NS; s++)
            *(float4*)(att + s * 512 + t * 4) = make_float4(av[s][0], av[s][1], av[s][2], av[s][3]);
    }
    __syncthreads();

    // phase 3: updates; warp owns 64 n, lane owns h-quad, 2 n per iteration
    float accU[NS][4];
#pragma unroll
    for (int s = 0; s < NS; s++)
#pragma unroll
        for (int e = 0; e < 4; e++) accU[s][e] = 0.f;
    int nsub = lane >> 4;
    int h4 = (lane & 15) * 4;
#pragma unroll 4
    for (int i = 0; i < 32; i++) {
        int n = w * 64 + 2 * i + nsub;
        float4 v4 = *(const float4*)(vB + (size_t)n * SD + h4);
#pragma unroll
        for (int s = 0; s < NS; s++) {
            float a = att[s * 512 + n];
            accU[s][0] += a * v4.x;
            accU[s][1] += a * v4.y;
            accU[s][2] += a * v4.z;
            accU[s][3] += a * v4.w;
        }
    }
#pragma unroll
    for (int s = 0; s < NS; s++)
#pragma unroll
        for (int e = 0; e < 4; e++)
            accU[s][e] += __shfl_xor_sync(0xffffffffu, accU[s][e], 16);
    float* pUw = lgp;   // lgp is dead now
    if (lane < 16) {
#pragma unroll
        for (int s = 0; s < NS; s++)
            *(float4*)(pUw + (w * NS + s) * 64 + h4) =
                make_float4(accU[s][0], accU[s][1], accU[s][2], accU[s][3]);
    }
    if (t < 128) {
#pragma unroll
        for (int s = 0; s < NS; s++) {
            float v = sred[s];
#pragma unroll
            for (int o = 16; o; o >>= 1) v += __shfl_xor_sync(0xffffffffu, v, o);
            if (lane == 0) srw[w * NS + s] = v;
        }
    }
    __syncthreads();

    for (int idx = t; idx < NS * SD; idx += 256) {
        int s = idx >> 6, h = idx & 63;
        float sum = 0.f;
#pragma unroll
        for (int w2 = 0; w2 < 8; w2++) sum += pUw[(w2 * NS + s) * 64 + h];
        g_pU[(((size_t)b * NCHUNK + chunk) * NS + s) * SD + h] = sum;
    }
    if (t < NS) {
        float ss = srw[t] + srw[NS + t] + srw[2 * NS + t] + srw[3 * NS + t];
        g_pS[((unsigned)b * NCHUNK + chunk) * NS + t] = ss;
    }
}

// ---------------- kernel 4: combine + GRU + MLP + LN + q (one batch per block) ----------------
__global__ __launch_bounds__(384) void update_kernel(const float* __restrict__ b_ih,
                                                     const float* __restrict__ b_hh,
                                                     const float* __restrict__ ln_mlp_g,
                                                     const float* __restrict__ ln_mlp_b,
                                                     const float* __restrict__ ln_slot_g,
                                                     const float* __restrict__ ln_slot_b,
                                                     const float* __restrict__ mlp_b1,
                                                     const float* __restrict__ mlp_b2,
                                                     float* __restrict__ out, int last) {
    __shared__ float S[NS];
    __shared__ float prev[NS * SD];
    __shared__ float upd[NS * SD];
    __shared__ float gi[NS * 192];
    __shared__ float gh[NS * 192];
    __shared__ float mln[NS * SD];
    __shared__ float m1[NS * 128];
    __shared__ float red[12][2];

    int b = blockIdx.x;
    int t = threadIdx.x;
    int s = t >> 6, h = t & 63;
    int wid = t >> 5, lane = t & 31;

    float u = 0.f;
#pragma unroll
    for (int c = 0; c < NCHUNK; c++)
        u += g_pU[(((unsigned)b * NCHUNK + c) * NS + s) * SD + h];
    if (h == 0) {
        float ss = 0.f;
#pragma unroll
        for (int c = 0; c < NCHUNK; c++) ss += g_pS[((unsigned)b * NCHUNK + c) * NS + s];
        S[s] = ss;
    }
    prev[t] = g_slots[b * 384 + t];
    __syncthreads();
    upd[t] = u / (S[s] + 1e-8f);
    __syncthreads();

#pragma unroll
    for (int g = 0; g < 6; g++) {
        int idx = t + g * 384;
        int half = idx / 1152;
        int r = idx - half * 1152;
        int s2 = r / 192, c = r - s2 * 192;
        const float* src = half ? prev : upd;
        const float* wT = half ? g_WhhT : g_WihT;
        float acc = half ? b_hh[c] : b_ih[c];
#pragma unroll
        for (int hh = 0; hh < SD; hh++) acc += src[s2 * SD + hh] * wT[hh * 192 + c];
        if (half) gh[s2 * 192 + c] = acc; else gi[s2 * 192 + c] = acc;
    }
    __syncthreads();

    float ir = gi[s * 192 + h], iz = gi[s * 192 + 64 + h], inn = gi[s * 192 + 128 + h];
    float hr = gh[s * 192 + h], hz = gh[s * 192 + 64 + h], hn = gh[s * 192 + 128 + h];
    float rg = 1.f / (1.f + expf(-(ir + hr)));
    float zg = 1.f / (1.f + expf(-(iz + hz)));
    float ng = tanhf(inn + rg * hn);
    float hv = (1.f - zg) * ng + zg * prev[t];

    {
        float sum = hv, sq = hv * hv;
        warp_red2(sum, sq);
        if (lane == 0) { red[wid][0] = sum; red[wid][1] = sq; }
    }
    __syncthreads();
    {
        float tsum = red[2 * s][0] + red[2 * s + 1][0];
        float tsq = red[2 * s][1] + red[2 * s + 1][1];
        float m = tsum * (1.f / 64.f);
        float var = tsq * (1.f / 64.f) - m * m;
        float rstd = rsqrtf(var + 1e-5f);
        mln[t] = (hv - m) * rstd * ln_mlp_g[h] + ln_mlp_b[h];
    }
    __syncthreads();

#pragma unroll
    for (int g = 0; g < 2; g++) {
        int idx = t + g * 384;
        int s2 = idx >> 7, c = idx & 127;
        float acc = mlp_b1[c];
#pragma unroll
        for (int hh = 0; hh < SD; hh++) acc += mln[s2 * SD + hh] * g_W1T[hh * 128 + c];
        m1[s2 * 128 + c] = fmaxf(acc, 0.f);
    }
    __syncthreads();

    float acc2 = mlp_b2[h];
#pragma unroll
    for (int c = 0; c < 128; c++) acc2 += m1[s * 128 + c] * g_W2T[c * SD + h];
    float snew = hv + acc2;
    g_slots[b * 384 + t] = snew;
    if (last) {
        out[b * 384 + t] = snew;
    } else {
        __syncthreads();
        {
            float sum = snew, sq = snew * snew;
            warp_red2(sum, sq);
            if (lane == 0) { red[wid][0] = sum; red[wid][1] = sq; }
        }
        __syncthreads();
        {
            float tsum = red[2 * s][0] + red[2 * s + 1][0];
            float tsq = red[2 * s][1] + red[2 * s + 1][1];
            float m = tsum * (1.f / 64.f);
            float var = tsq * (1.f / 64.f) - m * m;
            float rstd = rsqrtf(var + 1e-5f);
            mln[t] = (snew - m) * rstd * ln_slot_g[h] + ln_slot_b[h];
        }
        __syncthreads();
        float qv = 0.f;
#pragma unroll
        for (int hh = 0; hh < SD; hh++) qv += mln[s * SD + hh] * g_WqT[hh * SD + h];
        g_q[b * 384 + t] = qv;
    }
}

// ---------------- launch ----------------
extern "C" void kernel_launch(void* const* d_in, const int* in_sizes, int n_in,
                              void* d_out, int out_size) {
    const float* features   = (const float*)d_in[0];
    const float* slot_noise = (const float*)d_in[1];
    const float* slot_mu    = (const float*)d_in[2];
    const float* slot_sigma = (const float*)d_in[3];
    const float* ln_feat_g  = (const float*)d_in[4];
    const float* ln_feat_b  = (const float*)d_in[5];
    const float* ln_slot_g  = (const float*)d_in[6];
    const float* ln_slot_b  = (const float*)d_in[7];
    const float* ln_mlp_g   = (const float*)d_in[8];
    const float* ln_mlp_b   = (const float*)d_in[9];
    const float* Wk         = (const float*)d_in[10];
    const float* Wv         = (const float*)d_in[11];
    const float* Wq         = (const float*)d_in[12];
    const float* W_ih       = (const float*)d_in[13];
    const float* W_hh       = (const float*)d_in[14];
    const float* b_ih       = (const float*)d_in[15];
    const float* b_hh       = (const float*)d_in[16];
    const float* mlp_W1     = (const float*)d_in[17];
    const float* mlp_b1     = (const float*)d_in[18];
    const float* mlp_W2     = (const float*)d_in[19];
    const float* mlp_b2     = (const float*)d_in[20];
    float* out = (float*)d_out;

    cudaFuncSetAttribute(proj_mma_kernel, cudaFuncAttributeMaxDynamicSharedMemorySize, PROJ_SMEM);

    transpose_kernel<<<64, 256>>>(Wk, Wv, Wq, W_ih, W_hh, mlp_W1, mlp_W2, ln_feat_g, ln_feat_b);
    init_kernel<<<BB, 384>>>(slot_noise, slot_mu, slot_sigma, ln_slot_g, ln_slot_b);
    proj_mma_kernel<<<2048, 512, PROJ_SMEM>>>(features);
    for (int it = 0; it < 3; it++) {
        attn_kernel<<<BB * NCHUNK, 256>>>();
        update_kernel<<<BB, 384>>>(b_ih, b_hh, ln_mlp_g, ln_mlp_b, ln_slot_g, ln_slot_b,
                                   mlp_b1, mlp_b2, out, it == 2);
    }
}